// round 5
// baseline (speedup 1.0000x reference)
#include <cuda_runtime.h>
#include <math_constants.h>

#define BB 2
#define LL 384
#define DD 256
#define VV 32000
#define NLY 3
#define BL (BB*LL)

// ---------------- scratch (device globals; no allocation) ----------------
__device__ float g_real[BL*DD], g_imag[BL*DD];
__device__ float g_nr[BL*DD], g_ni[BL*DD], g_c[BL*DD], g_s[BL*DD];
__device__ float g_outr[BL*DD], g_outi[BL*DD];
__device__ float g_sc[BB*DD], g_ss[BB*DD];
__device__ float g_wmean[DD];
__device__ float g_scores[BB*LL*LL];
__device__ float g_A[BL*DD];
__device__ float g_weff[DD*VV];   // 32.8 MB

// ---------------- helpers ----------------
__device__ __forceinline__ float blockSum256(float v, float* sh) {
    int t = threadIdx.x;
    __syncthreads();
    sh[t] = v; __syncthreads();
    #pragma unroll
    for (int s = 128; s > 0; s >>= 1) {
        if (t < s) sh[t] += sh[t + s];
        __syncthreads();
    }
    return sh[0];
}

__device__ __forceinline__ float clip1(float v) { return fminf(fmaxf(v, -1.f), 1.f); }
__device__ __forceinline__ float sigm(float v) { return 1.f / (1.f + expf(-v)); }

__device__ __forceinline__ unsigned long long pk2(float a, float b) {
    unsigned long long r;
    asm("mov.b64 %0, {%1,%2};" : "=l"(r) : "r"(__float_as_uint(a)), "r"(__float_as_uint(b)));
    return r;
}
__device__ __forceinline__ void upk2(unsigned long long p, float& a, float& b) {
    unsigned int x, y;
    asm("mov.b64 {%0,%1}, %2;" : "=r"(x), "=r"(y) : "l"(p));
    a = __uint_as_float(x); b = __uint_as_float(y);
}
__device__ __forceinline__ void fma2(unsigned long long& d, unsigned long long a, unsigned long long b) {
    asm("fma.rn.f32x2 %0, %1, %2, %3;" : "=l"(d) : "l"(a), "l"(b), "l"(d));
}

// ---------------- K0: W_eff = out_w[:D] + out_w[D:] ----------------
__global__ void k_weff(const float* __restrict__ out_w) {
    int idx = blockIdx.x * 256 + threadIdx.x;          // idx = k*V + v
    g_weff[idx] = out_w[idx] + out_w[idx + DD*VV];
}

// ---------------- K1: embedding + phase space ----------------
__global__ void k_phase(const int* __restrict__ x, const float* __restrict__ emb_real,
                        const float* __restrict__ lp, const float* __restrict__ iw,
                        const float* __restrict__ energy, const float* __restrict__ excf) {
    __shared__ float sh[256];
    int row = blockIdx.x, d = threadIdx.x;
    int tok = x[row];
    float re = emb_real[tok*DD + d] * 0.1f;
    float fr = 0.f, fi = 0.f;
    const float cav[3] = {1.f, -0.5f, -0.5f};
    const float sav[3] = {0.f, 0.86602540378443865f, -0.86602540378443865f};
    const float PIPHI = 5.083203692315259f;
    #pragma unroll
    for (int i = 0; i < NLY; i++) {
        float pa = tanhf(lp[i*DD + d]) * PIPHI;
        float tr = re * cosf(pa);
        float ti = re * sinf(pa);
        float mu = blockSum256(tr, sh) * (1.f/DD);
        float dv = tr - mu;
        float var = blockSum256(dv*dv, sh) * (1.f/DD);
        float r = dv / sqrtf(var + 1e-8f);
        mu = blockSum256(ti, sh) * (1.f/DD);
        float di = ti - mu;
        var = blockSum256(di*di, sh) * (1.f/DD);
        float im = di / sqrtf(var + 1e-8f);
        float w = tanhf(iw[i*DD + d]);
        r *= w; im *= w;
        fr += r*cav[i] - im*sav[i];
        fi += r*sav[i] + im*cav[i];
    }
    float amp = sqrtf(fr*fr + fi*fi + 1e-8f);
    float exc = expf(energy[d]) * excf[0];
    if (amp < 0.1f) { fr += exc; fi += exc; }
    float nrm = sqrtf(fr*fr + fi*fi + 1e-8f);
    g_real[row*DD + d] = clip1(fr / nrm);
    g_imag[row*DD + d] = clip1(fi / nrm);
}

// ---------------- per-layer: wmean ----------------
__global__ void k_wmean(const float* __restrict__ W, int layer) {
    int d = threadIdx.x;
    const float* rowp = W + layer*DD*DD + d*DD;
    float s = 0.f;
    for (int j = 0; j < DD; j++) s += rowp[j];
    g_wmean[d] = s * (1.f/DD);
}

// ---------------- per-layer: q/k/v LN + phase trig ----------------
__global__ void k_norm() {
    __shared__ float sh[256];
    int row = blockIdx.x, d = threadIdx.x;
    float r = g_real[row*DD + d], im = g_imag[row*DD + d];
    float mu = blockSum256(r, sh) * (1.f/DD);
    float dv = r - mu;
    float var = blockSum256(dv*dv, sh) * (1.f/DD);
    float nr = dv / sqrtf(var + 1e-5f);
    mu = blockSum256(im, sh) * (1.f/DD);
    float di = im - mu;
    var = blockSum256(di*di, sh) * (1.f/DD);
    float ni = di / sqrtf(var + 1e-5f);
    float ph = atan2f(ni + 1e-8f, nr + 1e-8f);
    int idx = row*DD + d;
    g_nr[idx] = nr; g_ni[idx] = ni;
    g_c[idx] = cosf(ph); g_s[idx] = sinf(ph);
}

// ---------------- per-layer: column sums for coh ----------------
__global__ void k_colsum() {
    int b = blockIdx.x, d = threadIdx.x;
    float sc = 0.f, ss = 0.f;
    for (int m = 0; m < LL; m++) {
        int idx = (b*LL + m)*DD + d;
        sc += g_c[idx]; ss += g_s[idx];
    }
    g_sc[b*DD + d] = sc; g_ss[b*DD + d] = ss;
}

// ---------------- per-layer: scores (factorized interference) ----------------
__global__ void __launch_bounds__(256) k_scores(const int* __restrict__ x) {
    __shared__ float Ac[32][33], Ai[32][33], Bc[32][33], Bi[32][33];
    __shared__ float wm[DD];
    int b = blockIdx.z;
    int lt = blockIdx.y * 32, mt = blockIdx.x * 32;
    int t = threadIdx.x, tx = t & 31, ty = t >> 5;
    wm[t] = g_wmean[t];
    __syncthreads();
    float acc[4] = {0.f, 0.f, 0.f, 0.f};
    int lr = t >> 3, k4 = (t & 7) * 4;
    for (int kk = 0; kk < DD; kk += 32) {
        float4 cl = *(const float4*)&g_c[(b*LL + lt + lr)*DD + kk + k4];
        float4 sl = *(const float4*)&g_s[(b*LL + lt + lr)*DD + kk + k4];
        float4 cm = *(const float4*)&g_c[(b*LL + mt + lr)*DD + kk + k4];
        float4 sm = *(const float4*)&g_s[(b*LL + mt + lr)*DD + kk + k4];
        float4 w4 = *(const float4*)&wm[kk + k4];
        __syncthreads();
        Ac[lr][k4+0] = cl.x*w4.x; Ac[lr][k4+1] = cl.y*w4.y; Ac[lr][k4+2] = cl.z*w4.z; Ac[lr][k4+3] = cl.w*w4.w;
        Ai[lr][k4+0] = sl.x*w4.x; Ai[lr][k4+1] = sl.y*w4.y; Ai[lr][k4+2] = sl.z*w4.z; Ai[lr][k4+3] = sl.w*w4.w;
        Bc[lr][k4+0] = cm.x; Bc[lr][k4+1] = cm.y; Bc[lr][k4+2] = cm.z; Bc[lr][k4+3] = cm.w;
        Bi[lr][k4+0] = sm.x; Bi[lr][k4+1] = sm.y; Bi[lr][k4+2] = sm.z; Bi[lr][k4+3] = sm.w;
        __syncthreads();
        #pragma unroll
        for (int k = 0; k < 32; k++) {
            float bc = Bc[tx][k], bs = Bi[tx][k];
            #pragma unroll
            for (int j = 0; j < 4; j++) {
                int lj = ty + 8*j;
                acc[j] += Ac[lj][k]*bc + Ai[lj][k]*bs;
            }
        }
    }
    int mg = mt + tx;
    bool pad = (x[b*LL + mg] == 0);
    const float scale = 0.0625f; // D^-0.5
    #pragma unroll
    for (int j = 0; j < 4; j++) {
        int lg = lt + ty + 8*j;
        g_scores[(b*LL + lg)*LL + mg] = pad ? (-CUDART_INF_F) : acc[j]*scale;
    }
}

// ---------------- per-layer: softmax + clip (in place) ----------------
__global__ void k_softmax() {
    __shared__ float sh[128];
    int row = blockIdx.x, t = threadIdx.x;
    float* sc = &g_scores[row*LL];
    float v[3], mx = -CUDART_INF_F;
    #pragma unroll
    for (int r = 0; r < 3; r++) { v[r] = sc[t + 128*r]; mx = fmaxf(mx, v[r]); }
    sh[t] = mx; __syncthreads();
    #pragma unroll
    for (int s = 64; s > 0; s >>= 1) { if (t < s) sh[t] = fmaxf(sh[t], sh[t+s]); __syncthreads(); }
    mx = sh[0]; __syncthreads();
    float sum = 0.f;
    #pragma unroll
    for (int r = 0; r < 3; r++) { v[r] = expf(v[r] - mx); sum += v[r]; }
    sh[t] = sum; __syncthreads();
    #pragma unroll
    for (int s = 64; s > 0; s >>= 1) { if (t < s) sh[t] += sh[t+s]; __syncthreads(); }
    float inv = 1.f / sh[0];
    #pragma unroll
    for (int r = 0; r < 3; r++) {
        float p = v[r] * inv;
        sc[t + 128*r] = fminf(fmaxf(p, 1e-6f), 1.f);
    }
}

// ---------------- per-layer: out_r/out_i = attn @ nr/ni ----------------
__global__ void __launch_bounds__(256) k_out() {
    __shared__ float At[32][33], Nr[32][33], Ni[32][33];
    int b = blockIdx.z;
    int lt = blockIdx.y * 32, dt = blockIdx.x * 32;
    int t = threadIdx.x, tx = t & 31, ty = t >> 5;
    float ar[4] = {0.f,0.f,0.f,0.f}, ai[4] = {0.f,0.f,0.f,0.f};
    int lr = t >> 3, k4 = (t & 7) * 4;
    for (int mm = 0; mm < LL; mm += 32) {
        float4 a4 = *(const float4*)&g_scores[(b*LL + lt + lr)*LL + mm + k4];
        float4 r4 = *(const float4*)&g_nr[(b*LL + mm + lr)*DD + dt + k4];
        float4 i4 = *(const float4*)&g_ni[(b*LL + mm + lr)*DD + dt + k4];
        __syncthreads();
        At[lr][k4+0]=a4.x; At[lr][k4+1]=a4.y; At[lr][k4+2]=a4.z; At[lr][k4+3]=a4.w;
        Nr[lr][k4+0]=r4.x; Nr[lr][k4+1]=r4.y; Nr[lr][k4+2]=r4.z; Nr[lr][k4+3]=r4.w;
        Ni[lr][k4+0]=i4.x; Ni[lr][k4+1]=i4.y; Ni[lr][k4+2]=i4.z; Ni[lr][k4+3]=i4.w;
        __syncthreads();
        #pragma unroll
        for (int k = 0; k < 32; k++) {
            float nrv = Nr[k][tx], niv = Ni[k][tx];
            #pragma unroll
            for (int j = 0; j < 4; j++) {
                float a = At[ty + 8*j][k];
                ar[j] += a * nrv; ai[j] += a * niv;
            }
        }
    }
    #pragma unroll
    for (int j = 0; j < 4; j++) {
        int idx = (b*LL + lt + ty + 8*j)*DD + dt + tx;
        g_outr[idx] = ar[j]; g_outi[idx] = ai[j];
    }
}

// ---------------- per-layer: coherence + phase preservation + residual LN ----------------
__global__ void k_update(const float* __restrict__ pp, const float* __restrict__ cohf, int layer) {
    __shared__ float sh[256];
    int row = blockIdx.x, d = threadIdx.x;
    int b = row / LL;
    float c = g_c[row*DD + d], s = g_s[row*DD + d];
    float part = c * g_sc[b*DD + d] + s * g_ss[b*DD + d];
    float coh = blockSum256(part, sh) * (1.f / (float)(LL*DD));
    float cfv = sigm(cohf[layer]) * coh;
    float orv = g_outr[row*DD + d], oiv = g_outi[row*DD + d];
    float phase = atan2f(oiv + 1e-8f, orv + 1e-8f);
    float pres = sigm(pp[layer*DD + d]) * cfv;
    float pr = orv * cosf(phase * pres);
    float val = g_real[row*DD + d] + 0.01f * pr;
    float mu = blockSum256(val, sh) * (1.f/DD);
    float dv = val - mu;
    float var = blockSum256(dv*dv, sh) * (1.f/DD);
    float r = clip1(dv / sqrtf(var + 1e-8f));
    g_real[row*DD + d] = r;
    g_imag[row*DD + d] = r;   // reference bug: imag = real
}

// ---------------- final LN (concat of identical halves == LN over D) ----------------
__global__ void k_lnA() {
    __shared__ float sh[256];
    int row = blockIdx.x, d = threadIdx.x;
    float v = g_real[row*DD + d];
    float mu = blockSum256(v, sh) * (1.f/DD);
    float dv = v - mu;
    float var = blockSum256(dv*dv, sh) * (1.f/DD);
    g_A[row*DD + d] = dv / sqrtf(var + 1e-5f);
}

// ---------------- final GEMM: [768,256] @ [256,32000] with FFMA2 ----------------
__global__ void __launch_bounds__(256) k_gemm(const float* __restrict__ bias, float* __restrict__ out) {
    __shared__ float As[8][128];
    __shared__ float Bs[8][128];
    int bn = blockIdx.x * 128, bm = blockIdx.y * 128;
    int t = threadIdx.x, tx = t & 15, ty = t >> 4;
    unsigned long long acc[8][4];
    #pragma unroll
    for (int i = 0; i < 8; i++)
        #pragma unroll
        for (int j = 0; j < 4; j++) acc[i][j] = 0ULL;

    int ar = t >> 1, ak = (t & 1) * 4;         // A loader: row, k offset
    int bk = t >> 5, bnn = (t & 31) * 4;       // B loader: k row, n offset
    const float* Ap = &g_A[(bm + ar)*DD + ak];
    const float* Bp = &g_weff[(size_t)bk*VV + bn + bnn];

    for (int kk = 0; kk < DD; kk += 8) {
        float4 av = *(const float4*)(Ap + kk);
        float4 bv = *(const float4*)(Bp + (size_t)kk*VV);
        __syncthreads();
        As[ak+0][ar] = av.x; As[ak+1][ar] = av.y; As[ak+2][ar] = av.z; As[ak+3][ar] = av.w;
        *(float4*)&Bs[bk][bnn] = bv;
        __syncthreads();
        #pragma unroll
        for (int k = 0; k < 8; k++) {
            float4 a0 = *(const float4*)&As[k][ty*4];
            float4 a1 = *(const float4*)&As[k][64 + ty*4];
            ulonglong2 b0 = *(const ulonglong2*)&Bs[k][tx*4];
            ulonglong2 b1 = *(const ulonglong2*)&Bs[k][64 + tx*4];
            float aa[8] = {a0.x, a0.y, a0.z, a0.w, a1.x, a1.y, a1.z, a1.w};
            #pragma unroll
            for (int i = 0; i < 8; i++) {
                unsigned long long ap = pk2(aa[i], aa[i]);
                fma2(acc[i][0], ap, b0.x);
                fma2(acc[i][1], ap, b0.y);
                fma2(acc[i][2], ap, b1.x);
                fma2(acc[i][3], ap, b1.y);
            }
        }
    }

    float4 blo = *(const float4*)&bias[bn + tx*4];
    float4 bhi = *(const float4*)&bias[bn + 64 + tx*4];
    #pragma unroll
    for (int i = 0; i < 8; i++) {
        int r = bm + ((i < 4) ? (ty*4 + i) : (64 + ty*4 + i - 4));
        float f0, f1, f2, f3;
        upk2(acc[i][0], f0, f1); upk2(acc[i][1], f2, f3);
        float4 o;
        o.x = fminf(fmaxf((f0 + blo.x)*0.1f, -10.f), 10.f);
        o.y = fminf(fmaxf((f1 + blo.y)*0.1f, -10.f), 10.f);
        o.z = fminf(fmaxf((f2 + blo.z)*0.1f, -10.f), 10.f);
        o.w = fminf(fmaxf((f3 + blo.w)*0.1f, -10.f), 10.f);
        *(float4*)&out[(size_t)r*VV + bn + tx*4] = o;
        upk2(acc[i][2], f0, f1); upk2(acc[i][3], f2, f3);
        o.x = fminf(fmaxf((f0 + bhi.x)*0.1f, -10.f), 10.f);
        o.y = fminf(fmaxf((f1 + bhi.y)*0.1f, -10.f), 10.f);
        o.z = fminf(fmaxf((f2 + bhi.z)*0.1f, -10.f), 10.f);
        o.w = fminf(fmaxf((f3 + bhi.w)*0.1f, -10.f), 10.f);
        *(float4*)&out[(size_t)r*VV + bn + 64 + tx*4] = o;
    }
}

// ---------------- launch ----------------
extern "C" void kernel_launch(void* const* d_in, const int* in_sizes, int n_in,
                              void* d_out, int out_size) {
    const int*   x        = (const int*)  d_in[0];
    const float* emb_real = (const float*)d_in[1];
    // d_in[2] = emb_imag: unused downstream (as in reference)
    const float* lp       = (const float*)d_in[3];
    const float* iw       = (const float*)d_in[4];
    const float* energy   = (const float*)d_in[5];
    const float* excf     = (const float*)d_in[6];
    const float* pp       = (const float*)d_in[7];
    const float* cohf     = (const float*)d_in[8];
    const float* Wattn    = (const float*)d_in[9];
    const float* out_w    = (const float*)d_in[10];
    const float* out_b    = (const float*)d_in[11];
    float* out = (float*)d_out;

    k_weff<<<(DD*VV)/256, 256>>>(out_w);
    k_phase<<<BL, 256>>>(x, emb_real, lp, iw, energy, excf);
    for (int i = 0; i < NLY; i++) {
        k_wmean<<<1, 256>>>(Wattn, i);
        k_norm<<<BL, 256>>>();
        k_colsum<<<BB, 256>>>();
        k_scores<<<dim3(LL/32, LL/32, BB), 256>>>(x);
        k_softmax<<<BL, 128>>>();
        k_out<<<dim3(DD/32, LL/32, BB), 256>>>();
        k_update<<<BL, 256>>>(pp, cohf, i);
    }
    k_lnA<<<BL, 256>>>();
    k_gemm<<<dim3(VV/128, (BL)/128), 256>>>(out_b, out);
}

// round 6
// speedup vs baseline: 1.0051x; 1.0051x over previous
#include <cuda_runtime.h>
#include <math_constants.h>

#define BB 2
#define LL 384
#define DD 256
#define VV 32000
#define NLY 3
#define BL (BB*LL)

// ---------------- scratch (device globals; no allocation) ----------------
__device__ float g_real[BL*DD], g_imag[BL*DD];
__device__ float g_nr[BL*DD], g_ni[BL*DD], g_c[BL*DD], g_s[BL*DD];
__device__ float g_outr[BL*DD], g_outi[BL*DD];
__device__ float g_sc[BB*DD], g_ss[BB*DD];
__device__ float g_wmean[DD];
__device__ float g_scores[BB*LL*LL];
__device__ float g_A[BL*DD];
__device__ float g_weff[DD*VV];   // 32.8 MB

// ---------------- helpers ----------------
__device__ __forceinline__ float blockSum256(float v, float* sh) {
    int t = threadIdx.x;
    __syncthreads();
    sh[t] = v; __syncthreads();
    #pragma unroll
    for (int s = 128; s > 0; s >>= 1) {
        if (t < s) sh[t] += sh[t + s];
        __syncthreads();
    }
    return sh[0];
}

__device__ __forceinline__ float clip1(float v) { return fminf(fmaxf(v, -1.f), 1.f); }
__device__ __forceinline__ float sigm(float v) { return 1.f / (1.f + expf(-v)); }

__device__ __forceinline__ unsigned long long pk2(float a, float b) {
    unsigned long long r;
    asm("mov.b64 %0, {%1,%2};" : "=l"(r) : "r"(__float_as_uint(a)), "r"(__float_as_uint(b)));
    return r;
}
__device__ __forceinline__ void upk2(unsigned long long p, float& a, float& b) {
    unsigned int x, y;
    asm("mov.b64 {%0,%1}, %2;" : "=r"(x), "=r"(y) : "l"(p));
    a = __uint_as_float(x); b = __uint_as_float(y);
}
__device__ __forceinline__ void fma2(unsigned long long& d, unsigned long long a, unsigned long long b) {
    asm("fma.rn.f32x2 %0, %1, %2, %3;" : "=l"(d) : "l"(a), "l"(b), "l"(d));
}

// ---------------- K0: W_eff = out_w[:D] + out_w[D:] ----------------
__global__ void k_weff(const float* __restrict__ out_w) {
    int idx = blockIdx.x * 256 + threadIdx.x;          // idx = k*V + v
    g_weff[idx] = out_w[idx] + out_w[idx + DD*VV];
}

// ---------------- K1: embedding + phase space ----------------
__global__ void k_phase(const int* __restrict__ x, const float* __restrict__ emb_real,
                        const float* __restrict__ lp, const float* __restrict__ iw,
                        const float* __restrict__ energy, const float* __restrict__ excf) {
    __shared__ float sh[256];
    int row = blockIdx.x, d = threadIdx.x;
    int tok = x[row];
    float re = emb_real[tok*DD + d] * 0.1f;
    float fr = 0.f, fi = 0.f;
    const float cav[3] = {1.f, -0.5f, -0.5f};
    const float sav[3] = {0.f, 0.86602540378443865f, -0.86602540378443865f};
    const float PIPHI = 5.083203692315259f;
    #pragma unroll
    for (int i = 0; i < NLY; i++) {
        float pa = tanhf(lp[i*DD + d]) * PIPHI;
        float tr = re * cosf(pa);
        float ti = re * sinf(pa);
        float mu = blockSum256(tr, sh) * (1.f/DD);
        float dv = tr - mu;
        float var = blockSum256(dv*dv, sh) * (1.f/DD);
        float r = dv / sqrtf(var + 1e-8f);
        mu = blockSum256(ti, sh) * (1.f/DD);
        float di = ti - mu;
        var = blockSum256(di*di, sh) * (1.f/DD);
        float im = di / sqrtf(var + 1e-8f);
        float w = tanhf(iw[i*DD + d]);
        r *= w; im *= w;
        fr += r*cav[i] - im*sav[i];
        fi += r*sav[i] + im*cav[i];
    }
    float amp = sqrtf(fr*fr + fi*fi + 1e-8f);
    float exc = expf(energy[d]) * excf[0];
    if (amp < 0.1f) { fr += exc; fi += exc; }
    float nrm = sqrtf(fr*fr + fi*fi + 1e-8f);
    g_real[row*DD + d] = clip1(fr / nrm);
    g_imag[row*DD + d] = clip1(fi / nrm);
}

// ---------------- per-layer: wmean ----------------
__global__ void k_wmean(const float* __restrict__ W, int layer) {
    int d = threadIdx.x;
    const float* rowp = W + layer*DD*DD + d*DD;
    float s = 0.f;
    for (int j = 0; j < DD; j++) s += rowp[j];
    g_wmean[d] = s * (1.f/DD);
}

// ---------------- per-layer: q/k/v LN + phase trig ----------------
__global__ void k_norm() {
    __shared__ float sh[256];
    int row = blockIdx.x, d = threadIdx.x;
    float r = g_real[row*DD + d], im = g_imag[row*DD + d];
    float mu = blockSum256(r, sh) * (1.f/DD);
    float dv = r - mu;
    float var = blockSum256(dv*dv, sh) * (1.f/DD);
    float nr = dv / sqrtf(var + 1e-5f);
    mu = blockSum256(im, sh) * (1.f/DD);
    float di = im - mu;
    var = blockSum256(di*di, sh) * (1.f/DD);
    float ni = di / sqrtf(var + 1e-5f);
    float ph = atan2f(ni + 1e-8f, nr + 1e-8f);
    int idx = row*DD + d;
    g_nr[idx] = nr; g_ni[idx] = ni;
    g_c[idx] = cosf(ph); g_s[idx] = sinf(ph);
}

// ---------------- per-layer: column sums for coh ----------------
__global__ void k_colsum() {
    int b = blockIdx.x, d = threadIdx.x;
    float sc = 0.f, ss = 0.f;
    for (int m = 0; m < LL; m++) {
        int idx = (b*LL + m)*DD + d;
        sc += g_c[idx]; ss += g_s[idx];
    }
    g_sc[b*DD + d] = sc; g_ss[b*DD + d] = ss;
}

// ---------------- per-layer: scores (factorized interference) ----------------
__global__ void __launch_bounds__(256) k_scores(const int* __restrict__ x) {
    __shared__ float Ac[32][33], Ai[32][33], Bc[32][33], Bi[32][33];
    __shared__ float wm[DD];
    int b = blockIdx.z;
    int lt = blockIdx.y * 32, mt = blockIdx.x * 32;
    int t = threadIdx.x, tx = t & 31, ty = t >> 5;
    wm[t] = g_wmean[t];
    __syncthreads();
    float acc[4] = {0.f, 0.f, 0.f, 0.f};
    int lr = t >> 3, k4 = (t & 7) * 4;
    for (int kk = 0; kk < DD; kk += 32) {
        float4 cl = *(const float4*)&g_c[(b*LL + lt + lr)*DD + kk + k4];
        float4 sl = *(const float4*)&g_s[(b*LL + lt + lr)*DD + kk + k4];
        float4 cm = *(const float4*)&g_c[(b*LL + mt + lr)*DD + kk + k4];
        float4 sm = *(const float4*)&g_s[(b*LL + mt + lr)*DD + kk + k4];
        float4 w4 = *(const float4*)&wm[kk + k4];
        __syncthreads();
        Ac[lr][k4+0] = cl.x*w4.x; Ac[lr][k4+1] = cl.y*w4.y; Ac[lr][k4+2] = cl.z*w4.z; Ac[lr][k4+3] = cl.w*w4.w;
        Ai[lr][k4+0] = sl.x*w4.x; Ai[lr][k4+1] = sl.y*w4.y; Ai[lr][k4+2] = sl.z*w4.z; Ai[lr][k4+3] = sl.w*w4.w;
        Bc[lr][k4+0] = cm.x; Bc[lr][k4+1] = cm.y; Bc[lr][k4+2] = cm.z; Bc[lr][k4+3] = cm.w;
        Bi[lr][k4+0] = sm.x; Bi[lr][k4+1] = sm.y; Bi[lr][k4+2] = sm.z; Bi[lr][k4+3] = sm.w;
        __syncthreads();
        #pragma unroll
        for (int k = 0; k < 32; k++) {
            float bc = Bc[tx][k], bs = Bi[tx][k];
            #pragma unroll
            for (int j = 0; j < 4; j++) {
                int lj = ty + 8*j;
                acc[j] += Ac[lj][k]*bc + Ai[lj][k]*bs;
            }
        }
    }
    int mg = mt + tx;
    bool pad = (x[b*LL + mg] == 0);
    const float scale = 0.0625f; // D^-0.5
    #pragma unroll
    for (int j = 0; j < 4; j++) {
        int lg = lt + ty + 8*j;
        g_scores[(b*LL + lg)*LL + mg] = pad ? (-CUDART_INF_F) : acc[j]*scale;
    }
}

// ---------------- per-layer: softmax + clip (in place) ----------------
__global__ void k_softmax() {
    __shared__ float sh[128];
    int row = blockIdx.x, t = threadIdx.x;
    float* sc = &g_scores[row*LL];
    float v[3], mx = -CUDART_INF_F;
    #pragma unroll
    for (int r = 0; r < 3; r++) { v[r] = sc[t + 128*r]; mx = fmaxf(mx, v[r]); }
    sh[t] = mx; __syncthreads();
    #pragma unroll
    for (int s = 64; s > 0; s >>= 1) { if (t < s) sh[t] = fmaxf(sh[t], sh[t+s]); __syncthreads(); }
    mx = sh[0]; __syncthreads();
    float sum = 0.f;
    #pragma unroll
    for (int r = 0; r < 3; r++) { v[r] = expf(v[r] - mx); sum += v[r]; }
    sh[t] = sum; __syncthreads();
    #pragma unroll
    for (int s = 64; s > 0; s >>= 1) { if (t < s) sh[t] += sh[t+s]; __syncthreads(); }
    float inv = 1.f / sh[0];
    #pragma unroll
    for (int r = 0; r < 3; r++) {
        float p = v[r] * inv;
        sc[t + 128*r] = fminf(fmaxf(p, 1e-6f), 1.f);
    }
}

// ---------------- per-layer: out_r/out_i = attn @ nr/ni ----------------
__global__ void __launch_bounds__(256) k_out() {
    __shared__ float At[32][33], Nr[32][33], Ni[32][33];
    int b = blockIdx.z;
    int lt = blockIdx.y * 32, dt = blockIdx.x * 32;
    int t = threadIdx.x, tx = t & 31, ty = t >> 5;
    float ar[4] = {0.f,0.f,0.f,0.f}, ai[4] = {0.f,0.f,0.f,0.f};
    int lr = t >> 3, k4 = (t & 7) * 4;
    for (int mm = 0; mm < LL; mm += 32) {
        float4 a4 = *(const float4*)&g_scores[(b*LL + lt + lr)*LL + mm + k4];
        float4 r4 = *(const float4*)&g_nr[(b*LL + mm + lr)*DD + dt + k4];
        float4 i4 = *(const float4*)&g_ni[(b*LL + mm + lr)*DD + dt + k4];
        __syncthreads();
        At[lr][k4+0]=a4.x; At[lr][k4+1]=a4.y; At[lr][k4+2]=a4.z; At[lr][k4+3]=a4.w;
        Nr[lr][k4+0]=r4.x; Nr[lr][k4+1]=r4.y; Nr[lr][k4+2]=r4.z; Nr[lr][k4+3]=r4.w;
        Ni[lr][k4+0]=i4.x; Ni[lr][k4+1]=i4.y; Ni[lr][k4+2]=i4.z; Ni[lr][k4+3]=i4.w;
        __syncthreads();
        #pragma unroll
        for (int k = 0; k < 32; k++) {
            float nrv = Nr[k][tx], niv = Ni[k][tx];
            #pragma unroll
            for (int j = 0; j < 4; j++) {
                float a = At[ty + 8*j][k];
                ar[j] += a * nrv; ai[j] += a * niv;
            }
        }
    }
    #pragma unroll
    for (int j = 0; j < 4; j++) {
        int idx = (b*LL + lt + ty + 8*j)*DD + dt + tx;
        g_outr[idx] = ar[j]; g_outi[idx] = ai[j];
    }
}

// ---------------- per-layer: coherence + phase preservation + residual LN ----------------
__global__ void k_update(const float* __restrict__ pp, const float* __restrict__ cohf, int layer) {
    __shared__ float sh[256];
    int row = blockIdx.x, d = threadIdx.x;
    int b = row / LL;
    float c = g_c[row*DD + d], s = g_s[row*DD + d];
    float part = c * g_sc[b*DD + d] + s * g_ss[b*DD + d];
    float coh = blockSum256(part, sh) * (1.f / (float)(LL*DD));
    float cfv = sigm(cohf[layer]) * coh;
    float orv = g_outr[row*DD + d], oiv = g_outi[row*DD + d];
    float phase = atan2f(oiv + 1e-8f, orv + 1e-8f);
    float pres = sigm(pp[layer*DD + d]) * cfv;
    float pr = orv * cosf(phase * pres);
    float val = g_real[row*DD + d] + 0.01f * pr;
    float mu = blockSum256(val, sh) * (1.f/DD);
    float dv = val - mu;
    float var = blockSum256(dv*dv, sh) * (1.f/DD);
    float r = clip1(dv / sqrtf(var + 1e-8f));
    g_real[row*DD + d] = r;
    g_imag[row*DD + d] = r;   // reference bug: imag = real
}

// ---------------- final LN (concat of identical halves == LN over D) ----------------
__global__ void k_lnA() {
    __shared__ float sh[256];
    int row = blockIdx.x, d = threadIdx.x;
    float v = g_real[row*DD + d];
    float mu = blockSum256(v, sh) * (1.f/DD);
    float dv = v - mu;
    float var = blockSum256(dv*dv, sh) * (1.f/DD);
    g_A[row*DD + d] = dv / sqrtf(var + 1e-5f);
}

// ---------------- final GEMM: [768,256] @ [256,32000] with FFMA2 ----------------
__global__ void __launch_bounds__(256) k_gemm(const float* __restrict__ bias, float* __restrict__ out) {
    __shared__ float As[8][128];
    __shared__ float Bs[8][128];
    int bn = blockIdx.x * 128, bm = blockIdx.y * 128;
    int t = threadIdx.x, tx = t & 15, ty = t >> 4;
    unsigned long long acc[8][4];
    #pragma unroll
    for (int i = 0; i < 8; i++)
        #pragma unroll
        for (int j = 0; j < 4; j++) acc[i][j] = 0ULL;

    int ar = t >> 1, ak = (t & 1) * 4;         // A loader: row, k offset
    int bk = t >> 5, bnn = (t & 31) * 4;       // B loader: k row, n offset
    const float* Ap = &g_A[(bm + ar)*DD + ak];
    const float* Bp = &g_weff[(size_t)bk*VV + bn + bnn];

    for (int kk = 0; kk < DD; kk += 8) {
        float4 av = *(const float4*)(Ap + kk);
        float4 bv = *(const float4*)(Bp + (size_t)kk*VV);
        __syncthreads();
        As[ak+0][ar] = av.x; As[ak+1][ar] = av.y; As[ak+2][ar] = av.z; As[ak+3][ar] = av.w;
        *(float4*)&Bs[bk][bnn] = bv;
        __syncthreads();
        #pragma unroll
        for (int k = 0; k < 8; k++) {
            float4 a0 = *(const float4*)&As[k][ty*4];
            float4 a1 = *(const float4*)&As[k][64 + ty*4];
            ulonglong2 b0 = *(const ulonglong2*)&Bs[k][tx*4];
            ulonglong2 b1 = *(const ulonglong2*)&Bs[k][64 + tx*4];
            float aa[8] = {a0.x, a0.y, a0.z, a0.w, a1.x, a1.y, a1.z, a1.w};
            #pragma unroll
            for (int i = 0; i < 8; i++) {
                unsigned long long ap = pk2(aa[i], aa[i]);
                fma2(acc[i][0], ap, b0.x);
                fma2(acc[i][1], ap, b0.y);
                fma2(acc[i][2], ap, b1.x);
                fma2(acc[i][3], ap, b1.y);
            }
        }
    }

    float4 blo = *(const float4*)&bias[bn + tx*4];
    float4 bhi = *(const float4*)&bias[bn + 64 + tx*4];
    #pragma unroll
    for (int i = 0; i < 8; i++) {
        int r = bm + ((i < 4) ? (ty*4 + i) : (64 + ty*4 + i - 4));
        float f0, f1, f2, f3;
        upk2(acc[i][0], f0, f1); upk2(acc[i][1], f2, f3);
        float4 o;
        o.x = fminf(fmaxf((f0 + blo.x)*0.1f, -10.f), 10.f);
        o.y = fminf(fmaxf((f1 + blo.y)*0.1f, -10.f), 10.f);
        o.z = fminf(fmaxf((f2 + blo.z)*0.1f, -10.f), 10.f);
        o.w = fminf(fmaxf((f3 + blo.w)*0.1f, -10.f), 10.f);
        *(float4*)&out[(size_t)r*VV + bn + tx*4] = o;
        upk2(acc[i][2], f0, f1); upk2(acc[i][3], f2, f3);
        o.x = fminf(fmaxf((f0 + bhi.x)*0.1f, -10.f), 10.f);
        o.y = fminf(fmaxf((f1 + bhi.y)*0.1f, -10.f), 10.f);
        o.z = fminf(fmaxf((f2 + bhi.z)*0.1f, -10.f), 10.f);
        o.w = fminf(fmaxf((f3 + bhi.w)*0.1f, -10.f), 10.f);
        *(float4*)&out[(size_t)r*VV + bn + 64 + tx*4] = o;
    }
}

// ---------------- launch ----------------
extern "C" void kernel_launch(void* const* d_in, const int* in_sizes, int n_in,
                              void* d_out, int out_size) {
    const int*   x        = (const int*)  d_in[0];
    const float* emb_real = (const float*)d_in[1];
    // d_in[2] = emb_imag: unused downstream (as in reference)
    const float* lp       = (const float*)d_in[3];
    const float* iw       = (const float*)d_in[4];
    const float* energy   = (const float*)d_in[5];
    const float* excf     = (const float*)d_in[6];
    const float* pp       = (const float*)d_in[7];
    const float* cohf     = (const float*)d_in[8];
    const float* Wattn    = (const float*)d_in[9];
    const float* out_w    = (const float*)d_in[10];
    const float* out_b    = (const float*)d_in[11];
    float* out = (float*)d_out;

    k_weff<<<(DD*VV)/256, 256>>>(out_w);
    k_phase<<<BL, 256>>>(x, emb_real, lp, iw, energy, excf);
    for (int i = 0; i < NLY; i++) {
        k_wmean<<<1, 256>>>(Wattn, i);
        k_norm<<<BL, 256>>>();
        k_colsum<<<BB, 256>>>();
        k_scores<<<dim3(LL/32, LL/32, BB), 256>>>(x);
        k_softmax<<<BL, 128>>>();
        k_out<<<dim3(DD/32, LL/32, BB), 256>>>();
        k_update<<<BL, 256>>>(pp, cohf, i);
    }
    k_lnA<<<BL, 256>>>();
    k_gemm<<<dim3(VV/128, (BL)/128), 256>>>(out_b, out);
}

// round 11
// speedup vs baseline: 1.4322x; 1.4250x over previous
#include <cuda_runtime.h>
#include <cuda_bf16.h>
#include <math_constants.h>
#include <cstdint>

#define BB 2
#define LL 384
#define DD 256
#define VV 32000
#define NLY 3
#define BL (BB*LL)
#define KP 768   // split-K for bf16 gemm: [Ah|Al|Ah] x [Wh|Wh|Wl]

// ---------------- scratch (device globals; no allocation) ----------------
__device__ __align__(128) float g_real[BL*DD], g_imag[BL*DD];
__device__ __align__(128) float g_nr[BL*DD], g_ni[BL*DD], g_c[BL*DD], g_s[BL*DD];
__device__ __align__(128) float g_outr[BL*DD], g_outi[BL*DD];
__device__ __align__(128) float g_scp[BB*6*DD], g_ssp[BB*6*DD];
__device__ __align__(128) float g_wmean[NLY*DD];
__device__ __align__(128) float g_scores[BB*LL*LL];
__device__ __align__(128) __nv_bfloat16 g_aexp[BL*KP];
__device__ __align__(128) __nv_bfloat16 g_bt[(size_t)VV*KP];   // [v][k'] 49.2 MB

// ---------------- helpers ----------------
__device__ __forceinline__ float clip1(float v) { return fminf(fmaxf(v, -1.f), 1.f); }
__device__ __forceinline__ float sigm(float v) { return 1.f / (1.f + expf(-v)); }

// fused (sum, sumsq) reduction over 256 threads; sh must be float[16]
__device__ __forceinline__ void blockSum2(float a, float b, float* sh, float& oa, float& ob) {
    int lane = threadIdx.x & 31, w = threadIdx.x >> 5;
    #pragma unroll
    for (int o = 16; o; o >>= 1) {
        a += __shfl_xor_sync(0xffffffffu, a, o);
        b += __shfl_xor_sync(0xffffffffu, b, o);
    }
    __syncthreads();
    if (lane == 0) { sh[w] = a; sh[8 + w] = b; }
    __syncthreads();
    float sa = 0.f, sb = 0.f;
    #pragma unroll
    for (int i = 0; i < 8; i++) { sa += sh[i]; sb += sh[8 + i]; }
    oa = sa; ob = sb;
}

__device__ __forceinline__ uint32_t s2u(const void* p) {
    uint32_t a;
    asm("{ .reg .u64 t; cvta.to.shared.u64 t, %1; cvt.u32.u64 %0, t; }" : "=r"(a) : "l"(p));
    return a;
}

// ---------------- B split+transpose: g_bt[v][k'] from out_w ----------------
__global__ void __launch_bounds__(256) k_bsplit(const float* __restrict__ ow) {
    __shared__ float tile[32][33];
    int v0 = blockIdx.x * 32, k0 = blockIdx.y * 32;
    int tx = threadIdx.x & 31, ty = threadIdx.x >> 5;
    #pragma unroll
    for (int i = 0; i < 4; i++) {
        int k = k0 + ty + 8*i;
        tile[ty + 8*i][tx] = ow[(size_t)k*VV + v0 + tx] + ow[(size_t)(k + 256)*VV + v0 + tx];
    }
    __syncthreads();
    #pragma unroll
    for (int i = 0; i < 4; i++) {
        int v = v0 + ty + 8*i;
        float w = tile[tx][ty + 8*i];
        __nv_bfloat16 h = __float2bfloat16(w);
        __nv_bfloat16 l = __float2bfloat16(w - __bfloat162float(h));
        size_t base = (size_t)v*KP + k0 + tx;
        g_bt[base] = h;          // Wh
        g_bt[base + 256] = h;    // Wh (pairs with Al)
        g_bt[base + 512] = l;    // Wl (pairs with Ah)
    }
}

// ---------------- wmean for all layers ----------------
__global__ void k_wmean3(const float* __restrict__ W) {
    int l = blockIdx.x, t = threadIdx.x, lane = t & 31, w = t >> 5;
    for (int r = w; r < DD; r += 8) {
        const float* p = W + (size_t)l*DD*DD + (size_t)r*DD;
        float s = 0.f;
        #pragma unroll
        for (int j = 0; j < 8; j++) s += p[lane + 32*j];
        #pragma unroll
        for (int o = 16; o; o >>= 1) s += __shfl_xor_sync(0xffffffffu, s, o);
        if (lane == 0) g_wmean[l*DD + r] = s * (1.f/DD);
    }
}

// ---------------- embedding + phase space ----------------
__global__ void __launch_bounds__(256) k_phase(const int* __restrict__ x, const float* __restrict__ emb_real,
                        const float* __restrict__ lp, const float* __restrict__ iw,
                        const float* __restrict__ energy, const float* __restrict__ excf) {
    __shared__ float sh[16];
    int row = blockIdx.x, d = threadIdx.x;
    int tok = x[row];
    float re = emb_real[(size_t)tok*DD + d] * 0.1f;
    float fr = 0.f, fi = 0.f;
    const float cav[3] = {1.f, -0.5f, -0.5f};
    const float sav[3] = {0.f, 0.86602540378443865f, -0.86602540378443865f};
    const float PIPHI = 5.083203692315259f;
    #pragma unroll
    for (int i = 0; i < NLY; i++) {
        float pa = tanhf(lp[i*DD + d]) * PIPHI;
        float tr = re * cosf(pa);
        float ti = re * sinf(pa);
        float s1, s2;
        blockSum2(tr, tr*tr, sh, s1, s2);
        float mu = s1 * (1.f/DD);
        float r = (tr - mu) * rsqrtf(fmaxf(s2*(1.f/DD) - mu*mu, 0.f) + 1e-8f);
        blockSum2(ti, ti*ti, sh, s1, s2);
        mu = s1 * (1.f/DD);
        float im = (ti - mu) * rsqrtf(fmaxf(s2*(1.f/DD) - mu*mu, 0.f) + 1e-8f);
        float w = tanhf(iw[i*DD + d]);
        r *= w; im *= w;
        fr += r*cav[i] - im*sav[i];
        fi += r*sav[i] + im*cav[i];
    }
    float amp = sqrtf(fr*fr + fi*fi + 1e-8f);
    float exc = expf(energy[d]) * excf[0];
    if (amp < 0.1f) { fr += exc; fi += exc; }
    float nrm = rsqrtf(fr*fr + fi*fi + 1e-8f);
    g_real[row*DD + d] = clip1(fr * nrm);
    g_imag[row*DD + d] = clip1(fi * nrm);
}

// ---------------- per-layer: LN + unit phase vector (no trig) ----------------
__global__ void __launch_bounds__(256) k_norm(int first) {
    __shared__ float sh[16];
    int row = blockIdx.x, d = threadIdx.x;
    int idx = row*DD + d;
    float r = g_real[idx];
    float s1, s2;
    blockSum2(r, r*r, sh, s1, s2);
    float mu = s1 * (1.f/DD);
    float nr = (r - mu) * rsqrtf(fmaxf(s2*(1.f/DD) - mu*mu, 0.f) + 1e-5f);
    float ni;
    if (first) {
        float im = g_imag[idx];
        blockSum2(im, im*im, sh, s1, s2);
        mu = s1 * (1.f/DD);
        ni = (im - mu) * rsqrtf(fmaxf(s2*(1.f/DD) - mu*mu, 0.f) + 1e-5f);
    } else {
        ni = nr;   // imag == real after layer 0
    }
    float xx = nr + 1e-8f, yy = ni + 1e-8f;
    float h = rsqrtf(xx*xx + yy*yy);
    g_nr[idx] = nr; g_ni[idx] = ni;
    g_c[idx] = xx*h; g_s[idx] = yy*h;   // cos/sin(atan2(yy,xx))
}

// ---------------- per-layer: partial column sums for coherence ----------------
__global__ void k_colsum() {
    int b = blockIdx.x, ch = blockIdx.y, d = threadIdx.x;
    float sc = 0.f, ss = 0.f;
    #pragma unroll 4
    for (int m = ch*64; m < ch*64 + 64; m++) {
        int idx = (b*LL + m)*DD + d;
        sc += g_c[idx]; ss += g_s[idx];
    }
    g_scp[(b*6 + ch)*DD + d] = sc;
    g_ssp[(b*6 + ch)*DD + d] = ss;
}

// ---------------- per-layer: scores, 64x64 tile, 4x4 accum ----------------
__global__ void __launch_bounds__(256) k_scores(const int* __restrict__ x, int layer) {
    __shared__ float Ac[64][17], Ai[64][17], Bc[64][17], Bs[64][17];
    __shared__ float wm[DD];
    int b = blockIdx.z, lt = blockIdx.y*64, mt = blockIdx.x*64;
    int t = threadIdx.x, tx = t & 15, ty = t >> 4;
    wm[t] = g_wmean[layer*DD + t];
    __syncthreads();
    float acc[4][4] = {};
    int r = t >> 2, c4 = (t & 3) * 4;
    for (int kk = 0; kk < DD; kk += 16) {
        float4 cl = *(const float4*)&g_c[(b*LL + lt + r)*DD + kk + c4];
        float4 sl = *(const float4*)&g_s[(b*LL + lt + r)*DD + kk + c4];
        float4 cm = *(const float4*)&g_c[(b*LL + mt + r)*DD + kk + c4];
        float4 sm = *(const float4*)&g_s[(b*LL + mt + r)*DD + kk + c4];
        float4 w4 = *(const float4*)&wm[kk + c4];
        __syncthreads();
        Ac[r][c4+0]=cl.x*w4.x; Ac[r][c4+1]=cl.y*w4.y; Ac[r][c4+2]=cl.z*w4.z; Ac[r][c4+3]=cl.w*w4.w;
        Ai[r][c4+0]=sl.x*w4.x; Ai[r][c4+1]=sl.y*w4.y; Ai[r][c4+2]=sl.z*w4.z; Ai[r][c4+3]=sl.w*w4.w;
        Bc[r][c4+0]=cm.x; Bc[r][c4+1]=cm.y; Bc[r][c4+2]=cm.z; Bc[r][c4+3]=cm.w;
        Bs[r][c4+0]=sm.x; Bs[r][c4+1]=sm.y; Bs[r][c4+2]=sm.z; Bs[r][c4+3]=sm.w;
        __syncthreads();
        #pragma unroll
        for (int k = 0; k < 16; k++) {
            float a0[4], a1[4], b0[4], b1[4];
            #pragma unroll
            for (int i = 0; i < 4; i++) { a0[i] = Ac[ty+16*i][k]; a1[i] = Ai[ty+16*i][k]; }
            #pragma unroll
            for (int j = 0; j < 4; j++) { b0[j] = Bc[tx+16*j][k]; b1[j] = Bs[tx+16*j][k]; }
            #pragma unroll
            for (int i = 0; i < 4; i++)
                #pragma unroll
                for (int j = 0; j < 4; j++)
                    acc[i][j] += a0[i]*b0[j] + a1[i]*b1[j];
        }
    }
    #pragma unroll
    for (int j = 0; j < 4; j++) {
        int mg = mt + tx + 16*j;
        bool pad = (x[b*LL + mg] == 0);
        #pragma unroll
        for (int i = 0; i < 4; i++) {
            int lg = lt + ty + 16*i;
            g_scores[(b*LL + lg)*LL + mg] = pad ? (-CUDART_INF_F) : acc[i][j]*0.0625f;
        }
    }
}

// ---------------- per-layer: softmax + clip (in place) ----------------
__global__ void k_softmax() {
    __shared__ float sh[128];
    int row = blockIdx.x, t = threadIdx.x;
    float* sc = &g_scores[row*LL];
    float v[3], mx = -CUDART_INF_F;
    #pragma unroll
    for (int r = 0; r < 3; r++) { v[r] = sc[t + 128*r]; mx = fmaxf(mx, v[r]); }
    sh[t] = mx; __syncthreads();
    #pragma unroll
    for (int s = 64; s > 0; s >>= 1) { if (t < s) sh[t] = fmaxf(sh[t], sh[t+s]); __syncthreads(); }
    mx = sh[0]; __syncthreads();
    float sum = 0.f;
    #pragma unroll
    for (int r = 0; r < 3; r++) { v[r] = expf(v[r] - mx); sum += v[r]; }
    sh[t] = sum; __syncthreads();
    #pragma unroll
    for (int s = 64; s > 0; s >>= 1) { if (t < s) sh[t] += sh[t+s]; __syncthreads(); }
    float inv = 1.f / sh[0];
    #pragma unroll
    for (int r = 0; r < 3; r++) sc[t + 128*r] = fminf(fmaxf(v[r]*inv, 1e-6f), 1.f);
}

// ---------------- per-layer: out = attn @ [nr|ni], 64x64 tile ----------------
__global__ void __launch_bounds__(256) k_out() {
    __shared__ float At[64][17], Nr[16][68], Ni[16][68];
    int b = blockIdx.z, lt = blockIdx.y*64, dt = blockIdx.x*64;
    int t = threadIdx.x, tx = t & 15, ty = t >> 4;
    float ar[4][4] = {}, ai[4][4] = {};
    int r = t >> 2, c4 = (t & 3) * 4;       // At loader
    int kr = t >> 4, d4 = (t & 15) * 4;     // Nr/Ni loader
    for (int mm = 0; mm < LL; mm += 16) {
        float4 a4 = *(const float4*)&g_scores[(b*LL + lt + r)*LL + mm + c4];
        float4 r4 = *(const float4*)&g_nr[(b*LL + mm + kr)*DD + dt + d4];
        float4 i4 = *(const float4*)&g_ni[(b*LL + mm + kr)*DD + dt + d4];
        __syncthreads();
        At[r][c4+0]=a4.x; At[r][c4+1]=a4.y; At[r][c4+2]=a4.z; At[r][c4+3]=a4.w;
        Nr[kr][d4+0]=r4.x; Nr[kr][d4+1]=r4.y; Nr[kr][d4+2]=r4.z; Nr[kr][d4+3]=r4.w;
        Ni[kr][d4+0]=i4.x; Ni[kr][d4+1]=i4.y; Ni[kr][d4+2]=i4.z; Ni[kr][d4+3]=i4.w;
        __syncthreads();
        #pragma unroll
        for (int k = 0; k < 16; k++) {
            float at[4], nr4[4], ni4[4];
            #pragma unroll
            for (int i = 0; i < 4; i++) at[i] = At[ty+16*i][k];
            #pragma unroll
            for (int j = 0; j < 4; j++) { nr4[j] = Nr[k][tx+16*j]; ni4[j] = Ni[k][tx+16*j]; }
            #pragma unroll
            for (int i = 0; i < 4; i++)
                #pragma unroll
                for (int j = 0; j < 4; j++) {
                    ar[i][j] += at[i]*nr4[j];
                    ai[i][j] += at[i]*ni4[j];
                }
        }
    }
    #pragma unroll
    for (int i = 0; i < 4; i++)
        #pragma unroll
        for (int j = 0; j < 4; j++) {
            int idx = (b*LL + lt + ty + 16*i)*DD + dt + tx + 16*j;
            g_outr[idx] = ar[i][j]; g_outi[idx] = ai[i][j];
        }
}

// ---------------- per-layer: coherence + phase preservation + residual LN ----------------
__global__ void __launch_bounds__(256) k_update(const float* __restrict__ pp, const float* __restrict__ cohf, int layer) {
    __shared__ float sh[16];
    int row = blockIdx.x, d = threadIdx.x;
    int b = row / LL;
    float SC = 0.f, SS = 0.f;
    #pragma unroll
    for (int ch = 0; ch < 6; ch++) {
        SC += g_scp[(b*6 + ch)*DD + d];
        SS += g_ssp[(b*6 + ch)*DD + d];
    }
    float part = g_c[row*DD + d]*SC + g_s[row*DD + d]*SS;
    float s1, s2;
    blockSum2(part, part, sh, s1, s2);
    float coh = s1 * (1.f / (float)(LL*DD));
    float cfv = sigm(cohf[layer]) * coh;
    float orv = g_outr[row*DD + d], oiv = g_outi[row*DD + d];
    float phase = atan2f(oiv + 1e-8f, orv + 1e-8f);
    float pres = sigm(pp[layer*DD + d]) * cfv;
    float pr = orv * cosf(phase * pres);
    float val = g_real[row*DD + d] + 0.01f * pr;
    blockSum2(val, val*val, sh, s1, s2);
    float mu = s1 * (1.f/DD);
    float r = clip1((val - mu) * rsqrtf(fmaxf(s2*(1.f/DD) - mu*mu, 0.f) + 1e-8f));
    g_real[row*DD + d] = r;
    g_imag[row*DD + d] = r;   // reference bug: imag = real
}

// ---------------- final LN + bf16 hi/lo split of A ----------------
__global__ void __launch_bounds__(256) k_prepA() {
    __shared__ float sh[16];
    int row = blockIdx.x, d = threadIdx.x;
    float v = g_real[row*DD + d];
    float s1, s2;
    blockSum2(v, v*v, sh, s1, s2);
    float mu = s1 * (1.f/DD);
    float a = (v - mu) * rsqrtf(fmaxf(s2*(1.f/DD) - mu*mu, 0.f) + 1e-5f);
    __nv_bfloat16 h = __float2bfloat16(a);
    __nv_bfloat16 l = __float2bfloat16(a - __bfloat162float(h));
    size_t base = (size_t)row*KP + d;
    g_aexp[base] = h;          // Ah
    g_aexp[base + 256] = l;    // Al
    g_aexp[base + 512] = h;    // Ah (pairs with Wl)
}

// ---------------- final GEMM via mma.sync bf16 (HMMA; no tcgen05 on plain sm_103) ----
// CTA 128x128, 8 warps = 2(M) x 4(N), warp tile 64x32 = 4x4 m16n8k16
__global__ void __launch_bounds__(256) k_gemm_mma(const float* __restrict__ bias, float* __restrict__ out) {
    __shared__ __align__(128) __nv_bfloat16 sA[128*32];
    __shared__ __align__(128) __nv_bfloat16 sB[128*32];
    int t = threadIdx.x, lane = t & 31, wid = t >> 5;
    int wm = wid & 1, wn = wid >> 1;
    int bn = blockIdx.x * 128, bm = blockIdx.y * 128;
    const __nv_bfloat16* Ap = g_aexp + (size_t)bm*KP;
    const __nv_bfloat16* Bp = g_bt + (size_t)bn*KP;
    uint32_t sAu = s2u(sA), sBu = s2u(sB);

    float c[4][4][4];
    #pragma unroll
    for (int i = 0; i < 4; i++)
        #pragma unroll
        for (int j = 0; j < 4; j++)
            #pragma unroll
            for (int q = 0; q < 4; q++) c[i][j][q] = 0.f;

    // loader mapping: idx in [0,512): row = idx>>2 (0..127), 16B group g = idx&3
    int lr = t >> 2, lg = t & 3;
    uint32_t swA0 = (uint32_t)(lr*64 + ((lg ^ ((lr>>1)&3)) << 4));
    int lr1 = lr + 64;
    uint32_t swA1 = (uint32_t)(lr1*64 + ((lg ^ ((lr1>>1)&3)) << 4));

    // ldmatrix lane-address components
    int qa = lane >> 3, ra = lane & 7;
    int a_m_local = (qa & 1)*8 + ra;        // within 16-row tile
    int a_gsel = qa >> 1;                   // 0 or 1 (k sub-group)
    int lb = lane & 15;
    int qb = lb >> 3, rb = lb & 7;

    for (int ck = 0; ck < 24; ck++) {
        uint4 va0 = *(const uint4*)(Ap + (size_t)lr *KP + ck*32 + lg*8);
        uint4 va1 = *(const uint4*)(Ap + (size_t)lr1*KP + ck*32 + lg*8);
        uint4 vb0 = *(const uint4*)(Bp + (size_t)lr *KP + ck*32 + lg*8);
        uint4 vb1 = *(const uint4*)(Bp + (size_t)lr1*KP + ck*32 + lg*8);
        __syncthreads();
        *(uint4*)((char*)sA + swA0) = va0;
        *(uint4*)((char*)sA + swA1) = va1;
        *(uint4*)((char*)sB + swA0) = vb0;
        *(uint4*)((char*)sB + swA1) = vb1;
        __syncthreads();
        #pragma unroll
        for (int ks = 0; ks < 2; ks++) {
            uint32_t af[4][4];
            #pragma unroll
            for (int mt = 0; mt < 4; mt++) {
                int m = wm*64 + mt*16 + a_m_local;
                int g = ks*2 + a_gsel;
                uint32_t ad = sAu + (uint32_t)(m*64 + ((g ^ ((m>>1)&3)) << 4));
                asm volatile("ldmatrix.sync.aligned.m8n8.x4.shared.b16 {%0,%1,%2,%3}, [%4];"
                    : "=r"(af[mt][0]), "=r"(af[mt][1]), "=r"(af[mt][2]), "=r"(af[mt][3]) : "r"(ad));
            }
            uint32_t bf[4][2];
            #pragma unroll
            for (int nt = 0; nt < 4; nt++) {
                int n = wn*32 + nt*8 + rb;
                int g = ks*2 + qb;
                uint32_t bd = sBu + (uint32_t)(n*64 + ((g ^ ((n>>1)&3)) << 4));
                asm volatile("ldmatrix.sync.aligned.m8n8.x2.shared.b16 {%0,%1}, [%2];"
                    : "=r"(bf[nt][0]), "=r"(bf[nt][1]) : "r"(bd));
            }
            #pragma unroll
            for (int mt = 0; mt < 4; mt++)
                #pragma unroll
                for (int nt = 0; nt < 4; nt++) {
                    asm volatile(
                        "mma.sync.aligned.m16n8k16.row.col.f32.bf16.bf16.f32 "
                        "{%0,%1,%2,%3}, {%4,%5,%6,%7}, {%8,%9}, {%0,%1,%2,%3};"
                        : "+f"(c[mt][nt][0]), "+f"(c[mt][nt][1]), "+f"(c[mt][nt][2]), "+f"(c[mt][nt][3])
                        : "r"(af[mt][0]), "r"(af[mt][1]), "r"(af[mt][2]), "r"(af[mt][3]),
                          "r"(bf[nt][0]), "r"(bf[nt][1]));
                }
        }
    }

    // epilogue: bias + *0.1 + clip, float2 stores
    int rr0 = lane >> 2, cc0 = (lane & 3) * 2;
    #pragma unroll
    for (int mt = 0; mt < 4; mt++) {
        #pragma unroll
        for (int nt = 0; nt < 4; nt++) {
            int row = bm + wm*64 + mt*16 + rr0;
            int col = bn + wn*32 + nt*8 + cc0;
            float b0 = bias[col], b1 = bias[col + 1];
            float2 o;
            o.x = fminf(fmaxf((c[mt][nt][0] + b0)*0.1f, -10.f), 10.f);
            o.y = fminf(fmaxf((c[mt][nt][1] + b1)*0.1f, -10.f), 10.f);
            *(float2*)&out[(size_t)row*VV + col] = o;
            o.x = fminf(fmaxf((c[mt][nt][2] + b0)*0.1f, -10.f), 10.f);
            o.y = fminf(fmaxf((c[mt][nt][3] + b1)*0.1f, -10.f), 10.f);
            *(float2*)&out[(size_t)(row + 8)*VV + col] = o;
        }
    }
}

// ---------------- launch ----------------
extern "C" void kernel_launch(void* const* d_in, const int* in_sizes, int n_in,
                              void* d_out, int out_size) {
    const int*   x        = (const int*)  d_in[0];
    const float* emb_real = (const float*)d_in[1];
    // d_in[2] = emb_imag: unused downstream (as in reference)
    const float* lp       = (const float*)d_in[3];
    const float* iw       = (const float*)d_in[4];
    const float* energy   = (const float*)d_in[5];
    const float* excf     = (const float*)d_in[6];
    const float* pp       = (const float*)d_in[7];
    const float* cohf     = (const float*)d_in[8];
    const float* Wattn    = (const float*)d_in[9];
    const float* out_w    = (const float*)d_in[10];
    const float* out_b    = (const float*)d_in[11];
    float* out = (float*)d_out;

    k_bsplit<<<dim3(VV/32, DD/32), 256>>>(out_w);
    k_wmean3<<<NLY, 256>>>(Wattn);
    k_phase<<<BL, 256>>>(x, emb_real, lp, iw, energy, excf);
    for (int i = 0; i < NLY; i++) {
        k_norm<<<BL, 256>>>(i == 0 ? 1 : 0);
        k_colsum<<<dim3(BB, 6), 256>>>();
        k_scores<<<dim3(LL/64, LL/64, BB), 256>>>(x, i);
        k_softmax<<<BL, 128>>>();
        k_out<<<dim3(DD/64, LL/64, BB), 256>>>();
        k_update<<<BL, 256>>>(pp, cohf, i);
    }
    k_prepA<<<BL, 256>>>();
    k_gemm_mma<<<dim3(VV/128, BL/128), 256>>>(out_b, out);
}

// round 12
// speedup vs baseline: 1.9429x; 1.3566x over previous
#include <cuda_runtime.h>
#include <cuda_bf16.h>
#include <math_constants.h>
#include <cstdint>

#define BB 2
#define LL 384
#define DD 256
#define VV 32000
#define NLY 3
#define BL (BB*LL)
#define KP 768   // split-K for bf16 gemm: [Ah|Al|Ah] x [Wh|Wh|Wl]

// ---------------- scratch (device globals; no allocation) ----------------
__device__ __align__(128) float g_real[BL*DD], g_imag[BL*DD];
__device__ __align__(128) float g_c[BL*DD], g_s[BL*DD];
__device__ __align__(128) float g_outr[BL*DD], g_outi[BL*DD];
__device__ __align__(128) float g_scp[BB*6*DD], g_ssp[BB*6*DD];
__device__ __align__(128) float g_wmean[NLY*DD];
__device__ __align__(128) float g_scores[BB*LL*LL];
__device__ __align__(128) __nv_bfloat16 g_cw[BL*512];            // [row][cw|sw]
__device__ __align__(128) __nv_bfloat16 g_cs[BL*512];            // [row][c|s]
__device__ __align__(128) __nv_bfloat16 g_nT[BB*512*LL];         // [b][d(512)][m]: nr^T / ni^T
__device__ __align__(128) __nv_bfloat16 g_attnb[BB*LL*LL];       // [row l][m]
__device__ __align__(128) __nv_bfloat16 g_aexp[BL*KP];
__device__ __align__(128) __nv_bfloat16 g_bt[(size_t)VV*KP];     // [v][k'] 49.2 MB

// ---------------- helpers ----------------
__device__ __forceinline__ float clip1(float v) { return fminf(fmaxf(v, -1.f), 1.f); }
__device__ __forceinline__ float sigm(float v) { return 1.f / (1.f + expf(-v)); }

// fused (sum, sumsq) reduction over 256 threads; sh must be float[16]
__device__ __forceinline__ void blockSum2(float a, float b, float* sh, float& oa, float& ob) {
    int lane = threadIdx.x & 31, w = threadIdx.x >> 5;
    #pragma unroll
    for (int o = 16; o; o >>= 1) {
        a += __shfl_xor_sync(0xffffffffu, a, o);
        b += __shfl_xor_sync(0xffffffffu, b, o);
    }
    __syncthreads();
    if (lane == 0) { sh[w] = a; sh[8 + w] = b; }
    __syncthreads();
    float sa = 0.f, sb = 0.f;
    #pragma unroll
    for (int i = 0; i < 8; i++) { sa += sh[i]; sb += sh[8 + i]; }
    oa = sa; ob = sb;
}

__device__ __forceinline__ uint32_t s2u(const void* p) {
    uint32_t a;
    asm("{ .reg .u64 t; cvta.to.shared.u64 t, %1; cvt.u32.u64 %0, t; }" : "=r"(a) : "l"(p));
    return a;
}

// ---------------- shared bf16 HMMA mainloop ----------------
// CTA 128x128, 8 warps = 2(M) x 4(N), warp tile 64x32 = 4x4 m16n8k16.
// A: [128 rows][K] K-contig stride strA; B: [128 rows (=N cols)][K] stride strB.
// Register-prefetch double buffering over nc chunks of K=32.
__device__ __forceinline__ void gemm_mainloop(
    const __nv_bfloat16* __restrict__ Ap, int strA,
    const __nv_bfloat16* __restrict__ Bp, int strB,
    int nc, __nv_bfloat16* sA, __nv_bfloat16* sB, float (&c)[4][4][4])
{
    int t = threadIdx.x, lane = t & 31, wid = t >> 5;
    int wm = wid & 1, wn = wid >> 1;
    uint32_t sAu = s2u(sA), sBu = s2u(sB);

    int lr = t >> 2, lg = t & 3;
    uint32_t swA0 = (uint32_t)(lr*64 + ((lg ^ ((lr>>1)&3)) << 4));
    int lr1 = lr + 64;
    uint32_t swA1 = (uint32_t)(lr1*64 + ((lg ^ ((lr1>>1)&3)) << 4));

    int qa = lane >> 3, ra = lane & 7;
    int a_m_local = (qa & 1)*8 + ra;
    int a_gsel = qa >> 1;
    int lb = lane & 15;
    int qb = lb >> 3, rb = lb & 7;

    uint4 va0 = *(const uint4*)(Ap + (size_t)lr *strA + lg*8);
    uint4 va1 = *(const uint4*)(Ap + (size_t)lr1*strA + lg*8);
    uint4 vb0 = *(const uint4*)(Bp + (size_t)lr *strB + lg*8);
    uint4 vb1 = *(const uint4*)(Bp + (size_t)lr1*strB + lg*8);

    for (int ck = 0; ck < nc; ck++) {
        __syncthreads();
        *(uint4*)((char*)sA + swA0) = va0;
        *(uint4*)((char*)sA + swA1) = va1;
        *(uint4*)((char*)sB + swA0) = vb0;
        *(uint4*)((char*)sB + swA1) = vb1;
        __syncthreads();
        if (ck + 1 < nc) {
            int o = (ck + 1)*32 + lg*8;
            va0 = *(const uint4*)(Ap + (size_t)lr *strA + o);
            va1 = *(const uint4*)(Ap + (size_t)lr1*strA + o);
            vb0 = *(const uint4*)(Bp + (size_t)lr *strB + o);
            vb1 = *(const uint4*)(Bp + (size_t)lr1*strB + o);
        }
        #pragma unroll
        for (int ks = 0; ks < 2; ks++) {
            uint32_t af[4][4];
            #pragma unroll
            for (int mt = 0; mt < 4; mt++) {
                int m = wm*64 + mt*16 + a_m_local;
                int g = ks*2 + a_gsel;
                uint32_t ad = sAu + (uint32_t)(m*64 + ((g ^ ((m>>1)&3)) << 4));
                asm volatile("ldmatrix.sync.aligned.m8n8.x4.shared.b16 {%0,%1,%2,%3}, [%4];"
                    : "=r"(af[mt][0]), "=r"(af[mt][1]), "=r"(af[mt][2]), "=r"(af[mt][3]) : "r"(ad));
            }
            uint32_t bf[4][2];
            #pragma unroll
            for (int nt = 0; nt < 4; nt++) {
                int n = wn*32 + nt*8 + rb;
                int g = ks*2 + qb;
                uint32_t bd = sBu + (uint32_t)(n*64 + ((g ^ ((n>>1)&3)) << 4));
                asm volatile("ldmatrix.sync.aligned.m8n8.x2.shared.b16 {%0,%1}, [%2];"
                    : "=r"(bf[nt][0]), "=r"(bf[nt][1]) : "r"(bd));
            }
            #pragma unroll
            for (int mt = 0; mt < 4; mt++)
                #pragma unroll
                for (int nt = 0; nt < 4; nt++) {
                    asm volatile(
                        "mma.sync.aligned.m16n8k16.row.col.f32.bf16.bf16.f32 "
                        "{%0,%1,%2,%3}, {%4,%5,%6,%7}, {%8,%9}, {%0,%1,%2,%3};"
                        : "+f"(c[mt][nt][0]), "+f"(c[mt][nt][1]), "+f"(c[mt][nt][2]), "+f"(c[mt][nt][3])
                        : "r"(af[mt][0]), "r"(af[mt][1]), "r"(af[mt][2]), "r"(af[mt][3]),
                          "r"(bf[nt][0]), "r"(bf[nt][1]));
                }
        }
    }
}

// ---------------- B split+transpose: g_bt[v][k'] from out_w ----------------
__global__ void __launch_bounds__(256) k_bsplit(const float* __restrict__ ow) {
    __shared__ float tile[32][33];
    int v0 = blockIdx.x * 32, k0 = blockIdx.y * 32;
    int tx = threadIdx.x & 31, ty = threadIdx.x >> 5;
    #pragma unroll
    for (int i = 0; i < 4; i++) {
        int k = k0 + ty + 8*i;
        tile[ty + 8*i][tx] = ow[(size_t)k*VV + v0 + tx] + ow[(size_t)(k + 256)*VV + v0 + tx];
    }
    __syncthreads();
    #pragma unroll
    for (int i = 0; i < 4; i++) {
        int v = v0 + ty + 8*i;
        float w = tile[tx][ty + 8*i];
        __nv_bfloat16 h = __float2bfloat16(w);
        __nv_bfloat16 l = __float2bfloat16(w - __bfloat162float(h));
        size_t base = (size_t)v*KP + k0 + tx;
        g_bt[base] = h;          // Wh
        g_bt[base + 256] = h;    // Wh (pairs with Al)
        g_bt[base + 512] = l;    // Wl (pairs with Ah)
    }
}

// ---------------- wmean for all layers ----------------
__global__ void k_wmean3(const float* __restrict__ W) {
    int l = blockIdx.x, t = threadIdx.x, lane = t & 31, w = t >> 5;
    for (int r = w; r < DD; r += 8) {
        const float* p = W + (size_t)l*DD*DD + (size_t)r*DD;
        float s = 0.f;
        #pragma unroll
        for (int j = 0; j < 8; j++) s += p[lane + 32*j];
        #pragma unroll
        for (int o = 16; o; o >>= 1) s += __shfl_xor_sync(0xffffffffu, s, o);
        if (lane == 0) g_wmean[l*DD + r] = s * (1.f/DD);
    }
}

// ---------------- embedding + phase space ----------------
__global__ void __launch_bounds__(256) k_phase(const int* __restrict__ x, const float* __restrict__ emb_real,
                        const float* __restrict__ lp, const float* __restrict__ iw,
                        const float* __restrict__ energy, const float* __restrict__ excf) {
    __shared__ float sh[16];
    int row = blockIdx.x, d = threadIdx.x;
    int tok = x[row];
    float re = emb_real[(size_t)tok*DD + d] * 0.1f;
    float fr = 0.f, fi = 0.f;
    const float cav[3] = {1.f, -0.5f, -0.5f};
    const float sav[3] = {0.f, 0.86602540378443865f, -0.86602540378443865f};
    const float PIPHI = 5.083203692315259f;
    #pragma unroll
    for (int i = 0; i < NLY; i++) {
        float pa = tanhf(lp[i*DD + d]) * PIPHI;
        float tr = re * cosf(pa);
        float ti = re * sinf(pa);
        float s1, s2;
        blockSum2(tr, tr*tr, sh, s1, s2);
        float mu = s1 * (1.f/DD);
        float r = (tr - mu) * rsqrtf(fmaxf(s2*(1.f/DD) - mu*mu, 0.f) + 1e-8f);
        blockSum2(ti, ti*ti, sh, s1, s2);
        mu = s1 * (1.f/DD);
        float im = (ti - mu) * rsqrtf(fmaxf(s2*(1.f/DD) - mu*mu, 0.f) + 1e-8f);
        float w = tanhf(iw[i*DD + d]);
        r *= w; im *= w;
        fr += r*cav[i] - im*sav[i];
        fi += r*sav[i] + im*cav[i];
    }
    float amp = sqrtf(fr*fr + fi*fi + 1e-8f);
    float exc = expf(energy[d]) * excf[0];
    if (amp < 0.1f) { fr += exc; fi += exc; }
    float nrm = rsqrtf(fr*fr + fi*fi + 1e-8f);
    g_real[row*DD + d] = clip1(fr * nrm);
    g_imag[row*DD + d] = clip1(fi * nrm);
}

// ---------------- per-layer: LN + operand staging (bf16) ----------------
__global__ void __launch_bounds__(256) k_norm(int layer, int first) {
    __shared__ float sh[16];
    int row = blockIdx.x, d = threadIdx.x;
    int b = row / LL, l = row % LL;
    int idx = row*DD + d;
    float r = g_real[idx];
    float s1, s2;
    blockSum2(r, r*r, sh, s1, s2);
    float mu = s1 * (1.f/DD);
    float nr = (r - mu) * rsqrtf(fmaxf(s2*(1.f/DD) - mu*mu, 0.f) + 1e-5f);
    float ni;
    if (first) {
        float im = g_imag[idx];
        blockSum2(im, im*im, sh, s1, s2);
        mu = s1 * (1.f/DD);
        ni = (im - mu) * rsqrtf(fmaxf(s2*(1.f/DD) - mu*mu, 0.f) + 1e-5f);
    } else {
        ni = nr;   // imag == real after layer 0
    }
    float xx = nr + 1e-8f, yy = ni + 1e-8f;
    float h = rsqrtf(xx*xx + yy*yy);
    float cc = xx*h, ss = yy*h;   // cos/sin(atan2(yy,xx))
    g_c[idx] = cc; g_s[idx] = ss;
    float wm = g_wmean[layer*DD + d];
    // scores operands: A row = [c*w | s*w], B row = [c | s]
    g_cw[row*512 + d]       = __float2bfloat16(cc*wm);
    g_cw[row*512 + 256 + d] = __float2bfloat16(ss*wm);
    g_cs[row*512 + d]       = __float2bfloat16(cc);
    g_cs[row*512 + 256 + d] = __float2bfloat16(ss);
    // out-GEMM B operand: transposed nr/ni
    g_nT[(size_t)b*512*LL + (size_t)d*LL + l]         = __float2bfloat16(nr);
    g_nT[(size_t)b*512*LL + (size_t)(256 + d)*LL + l] = __float2bfloat16(ni);
}

// ---------------- per-layer: partial column sums for coherence ----------------
__global__ void k_colsum() {
    int b = blockIdx.x, ch = blockIdx.y, d = threadIdx.x;
    float sc = 0.f, ss = 0.f;
    #pragma unroll 4
    for (int m = ch*64; m < ch*64 + 64; m++) {
        int idx = (b*LL + m)*DD + d;
        sc += g_c[idx]; ss += g_s[idx];
    }
    g_scp[(b*6 + ch)*DD + d] = sc;
    g_ssp[(b*6 + ch)*DD + d] = ss;
}

// ---------------- per-layer: scores via HMMA (M=N=384, K=512 per batch) ----------------
__global__ void __launch_bounds__(256) k_scores_mma(const int* __restrict__ x) {
    __shared__ __align__(128) __nv_bfloat16 sA[128*32];
    __shared__ __align__(128) __nv_bfloat16 sB[128*32];
    int b = blockIdx.z, bm = blockIdx.y*128, bn = blockIdx.x*128;
    float c[4][4][4];
    #pragma unroll
    for (int i = 0; i < 4; i++)
        #pragma unroll
        for (int j = 0; j < 4; j++)
            #pragma unroll
            for (int q = 0; q < 4; q++) c[i][j][q] = 0.f;
    gemm_mainloop(g_cw + (size_t)(b*LL + bm)*512, 512,
                  g_cs + (size_t)(b*LL + bn)*512, 512,
                  16, sA, sB, c);
    int lane = threadIdx.x & 31, wid = threadIdx.x >> 5;
    int wm = wid & 1, wn = wid >> 1;
    int rr0 = lane >> 2, cc0 = (lane & 3)*2;
    #pragma unroll
    for (int mt = 0; mt < 4; mt++)
        #pragma unroll
        for (int nt = 0; nt < 4; nt++) {
            int row = bm + wm*64 + mt*16 + rr0;
            int col = bn + wn*32 + nt*8 + cc0;
            bool p0 = (x[b*LL + col] == 0), p1 = (x[b*LL + col + 1] == 0);
            float2 o;
            o.x = p0 ? (-CUDART_INF_F) : c[mt][nt][0]*0.0625f;
            o.y = p1 ? (-CUDART_INF_F) : c[mt][nt][1]*0.0625f;
            *(float2*)&g_scores[(size_t)(b*LL + row)*LL + col] = o;
            o.x = p0 ? (-CUDART_INF_F) : c[mt][nt][2]*0.0625f;
            o.y = p1 ? (-CUDART_INF_F) : c[mt][nt][3]*0.0625f;
            *(float2*)&g_scores[(size_t)(b*LL + row + 8)*LL + col] = o;
        }
}

// ---------------- per-layer: softmax + clip -> bf16 attn ----------------
__global__ void k_softmax() {
    __shared__ float sh[128];
    int row = blockIdx.x, t = threadIdx.x;
    const float* sc = &g_scores[(size_t)row*LL];
    float v[3], mx = -CUDART_INF_F;
    #pragma unroll
    for (int r = 0; r < 3; r++) { v[r] = sc[t + 128*r]; mx = fmaxf(mx, v[r]); }
    sh[t] = mx; __syncthreads();
    #pragma unroll
    for (int s = 64; s > 0; s >>= 1) { if (t < s) sh[t] = fmaxf(sh[t], sh[t+s]); __syncthreads(); }
    mx = sh[0]; __syncthreads();
    float sum = 0.f;
    #pragma unroll
    for (int r = 0; r < 3; r++) { v[r] = expf(v[r] - mx); sum += v[r]; }
    sh[t] = sum; __syncthreads();
    #pragma unroll
    for (int s = 64; s > 0; s >>= 1) { if (t < s) sh[t] += sh[t+s]; __syncthreads(); }
    float inv = 1.f / sh[0];
    #pragma unroll
    for (int r = 0; r < 3; r++) {
        float p = fminf(fmaxf(v[r]*inv, 1e-6f), 1.f);
        g_attnb[(size_t)row*LL + t + 128*r] = __float2bfloat16(p);
    }
}

// ---------------- per-layer: out = attn @ [nr|ni]^T via HMMA (M=384,N=512,K=384) ----------------
__global__ void __launch_bounds__(256) k_out_mma() {
    __shared__ __align__(128) __nv_bfloat16 sA[128*32];
    __shared__ __align__(128) __nv_bfloat16 sB[128*32];
    int b = blockIdx.z, bm = blockIdx.y*128, bn = blockIdx.x*128;
    float c[4][4][4];
    #pragma unroll
    for (int i = 0; i < 4; i++)
        #pragma unroll
        for (int j = 0; j < 4; j++)
            #pragma unroll
            for (int q = 0; q < 4; q++) c[i][j][q] = 0.f;
    gemm_mainloop(g_attnb + (size_t)(b*LL + bm)*LL, LL,
                  g_nT + (size_t)b*512*LL + (size_t)bn*LL, LL,
                  12, sA, sB, c);
    int lane = threadIdx.x & 31, wid = threadIdx.x >> 5;
    int wm = wid & 1, wn = wid >> 1;
    int rr0 = lane >> 2, cc0 = (lane & 3)*2;
    float* dst = (bn < 256) ? g_outr : g_outi;
    int nb = (bn < 256) ? bn : (bn - 256);
    #pragma unroll
    for (int mt = 0; mt < 4; mt++)
        #pragma unroll
        for (int nt = 0; nt < 4; nt++) {
            int row = bm + wm*64 + mt*16 + rr0;
            int col = nb + wn*32 + nt*8 + cc0;
            float2 o;
            o.x = c[mt][nt][0]; o.y = c[mt][nt][1];
            *(float2*)&dst[(size_t)(b*LL + row)*DD + col] = o;
            o.x = c[mt][nt][2]; o.y = c[mt][nt][3];
            *(float2*)&dst[(size_t)(b*LL + row + 8)*DD + col] = o;
        }
}

// ---------------- per-layer: coherence + phase preservation + residual LN ----------------
__global__ void __launch_bounds__(256) k_update(const float* __restrict__ pp, const float* __restrict__ cohf, int layer) {
    __shared__ float sh[16];
    int row = blockIdx.x, d = threadIdx.x;
    int b = row / LL;
    float SC = 0.f, SS = 0.f;
    #pragma unroll
    for (int ch = 0; ch < 6; ch++) {
        SC += g_scp[(b*6 + ch)*DD + d];
        SS += g_ssp[(b*6 + ch)*DD + d];
    }
    float part = g_c[row*DD + d]*SC + g_s[row*DD + d]*SS;
    float s1, s2;
    blockSum2(part, part, sh, s1, s2);
    float coh = s1 * (1.f / (float)(LL*DD));
    float cfv = sigm(cohf[layer]) * coh;
    float orv = g_outr[row*DD + d], oiv = g_outi[row*DD + d];
    float phase = atan2f(oiv + 1e-8f, orv + 1e-8f);
    float pres = sigm(pp[layer*DD + d]) * cfv;
    float pr = orv * cosf(phase * pres);
    float val = g_real[row*DD + d] + 0.01f * pr;
    blockSum2(val, val*val, sh, s1, s2);
    float mu = s1 * (1.f/DD);
    float r = clip1((val - mu) * rsqrtf(fmaxf(s2*(1.f/DD) - mu*mu, 0.f) + 1e-8f));
    g_real[row*DD + d] = r;
    g_imag[row*DD + d] = r;   // reference bug: imag = real
}

// ---------------- final LN + bf16 hi/lo split of A ----------------
__global__ void __launch_bounds__(256) k_prepA() {
    __shared__ float sh[16];
    int row = blockIdx.x, d = threadIdx.x;
    float v = g_real[row*DD + d];
    float s1, s2;
    blockSum2(v, v*v, sh, s1, s2);
    float mu = s1 * (1.f/DD);
    float a = (v - mu) * rsqrtf(fmaxf(s2*(1.f/DD) - mu*mu, 0.f) + 1e-5f);
    __nv_bfloat16 h = __float2bfloat16(a);
    __nv_bfloat16 l = __float2bfloat16(a - __bfloat162float(h));
    size_t base = (size_t)row*KP + d;
    g_aexp[base] = h;          // Ah
    g_aexp[base + 256] = l;    // Al
    g_aexp[base + 512] = h;    // Ah (pairs with Wl)
}

// ---------------- final GEMM via HMMA: C[768,32000] ----------------
__global__ void __launch_bounds__(256) k_gemm_mma(const float* __restrict__ bias, float* __restrict__ out) {
    __shared__ __align__(128) __nv_bfloat16 sA[128*32];
    __shared__ __align__(128) __nv_bfloat16 sB[128*32];
    int bn = blockIdx.x * 128, bm = blockIdx.y * 128;
    float c[4][4][4];
    #pragma unroll
    for (int i = 0; i < 4; i++)
        #pragma unroll
        for (int j = 0; j < 4; j++)
            #pragma unroll
            for (int q = 0; q < 4; q++) c[i][j][q] = 0.f;
    gemm_mainloop(g_aexp + (size_t)bm*KP, KP,
                  g_bt + (size_t)bn*KP, KP,
                  24, sA, sB, c);
    int lane = threadIdx.x & 31, wid = threadIdx.x >> 5;
    int wm = wid & 1, wn = wid >> 1;
    int rr0 = lane >> 2, cc0 = (lane & 3)*2;
    #pragma unroll
    for (int mt = 0; mt < 4; mt++) {
        #pragma unroll
        for (int nt = 0; nt < 4; nt++) {
            int row = bm + wm*64 + mt*16 + rr0;
            int col = bn + wn*32 + nt*8 + cc0;
            float b0 = bias[col], b1 = bias[col + 1];
            float2 o;
            o.x = fminf(fmaxf((c[mt][nt][0] + b0)*0.1f, -10.f), 10.f);
            o.y = fminf(fmaxf((c[mt][nt][1] + b1)*0.1f, -10.f), 10.f);
            *(float2*)&out[(size_t)row*VV + col] = o;
            o.x = fminf(fmaxf((c[mt][nt][2] + b0)*0.1f, -10.f), 10.f);
            o.y = fminf(fmaxf((c[mt][nt][3] + b1)*0.1f, -10.f), 10.f);
            *(float2*)&out[(size_t)(row + 8)*VV + col] = o;
        }
    }
}

// ---------------- launch ----------------
extern "C" void kernel_launch(void* const* d_in, const int* in_sizes, int n_in,
                              void* d_out, int out_size) {
    const int*   x        = (const int*)  d_in[0];
    const float* emb_real = (const float*)d_in[1];
    // d_in[2] = emb_imag: unused downstream (as in reference)
    const float* lp       = (const float*)d_in[3];
    const float* iw       = (const float*)d_in[4];
    const float* energy   = (const float*)d_in[5];
    const float* excf     = (const float*)d_in[6];
    const float* pp       = (const float*)d_in[7];
    const float* cohf     = (const float*)d_in[8];
    const float* Wattn    = (const float*)d_in[9];
    const float* out_w    = (const float*)d_in[10];
    const float* out_b    = (const float*)d_in[11];
    float* out = (float*)d_out;

    k_bsplit<<<dim3(VV/32, DD/32), 256>>>(out_w);
    k_wmean3<<<NLY, 256>>>(Wattn);
    k_phase<<<BL, 256>>>(x, emb_real, lp, iw, energy, excf);
    for (int i = 0; i < NLY; i++) {
        k_norm<<<BL, 256>>>(i, i == 0 ? 1 : 0);
        k_colsum<<<dim3(BB, 6), 256>>>();
        k_scores_mma<<<dim3(LL/128, LL/128, BB), 256>>>(x);
        k_softmax<<<BL, 128>>>();
        k_out_mma<<<dim3(512/128, LL/128, BB), 256>>>();
        k_update<<<BL, 256>>>(pp, cohf, i);
    }
    k_prepA<<<BL, 256>>>();
    k_gemm_mma<<<dim3(VV/128, BL/128), 256>>>(out_b, out);
}

// round 14
// speedup vs baseline: 2.3225x; 1.1954x over previous
#include <cuda_runtime.h>
#include <cuda_bf16.h>
#include <math_constants.h>
#include <cstdint>

#define BB 2
#define LL 384
#define DD 256
#define VV 32000
#define NLY 3
#define BL (BB*LL)
#define KP 768   // split-K for bf16 gemm: [Ah|Al|Ah] x [Wh|Wh|Wl]

// ---------------- scratch (device globals; no allocation) ----------------
__device__ __align__(128) float g_real[BL*DD], g_imag[BL*DD];
__device__ __align__(128) float g_c[BL*DD], g_s[BL*DD];
__device__ __align__(128) float g_outr[BL*DD], g_outi[BL*DD];
__device__ __align__(128) float g_scp[BB*6*DD], g_ssp[BB*6*DD];
__device__ __align__(128) float g_wmean[NLY*DD];
__device__ __align__(128) float g_scores[BB*LL*LL];
__device__ __align__(128) __nv_bfloat16 g_cw[BL*512];            // [row][cw|sw]
__device__ __align__(128) __nv_bfloat16 g_cs[BL*512];            // [row][c|s]
__device__ __align__(128) __nv_bfloat16 g_nb[BL*512];            // [row][nr|ni] (coalesced)
__device__ __align__(128) __nv_bfloat16 g_nT[BB*512*LL];         // [b][d(512)][m]
__device__ __align__(128) __nv_bfloat16 g_attnb[BB*LL*LL];       // [row l][m]
__device__ __align__(128) __nv_bfloat16 g_aexp[BL*KP];
__device__ __align__(128) __nv_bfloat16 g_bt[(size_t)VV*KP];     // [v][k'] 49.2 MB

// ---------------- helpers ----------------
__device__ __forceinline__ float clip1(float v) { return fminf(fmaxf(v, -1.f), 1.f); }
__device__ __forceinline__ float sigm(float v) { return 1.f / (1.f + expf(-v)); }

__device__ __forceinline__ void blockSum2(float a, float b, float* sh, float& oa, float& ob) {
    int lane = threadIdx.x & 31, w = threadIdx.x >> 5;
    #pragma unroll
    for (int o = 16; o; o >>= 1) {
        a += __shfl_xor_sync(0xffffffffu, a, o);
        b += __shfl_xor_sync(0xffffffffu, b, o);
    }
    __syncthreads();
    if (lane == 0) { sh[w] = a; sh[8 + w] = b; }
    __syncthreads();
    float sa = 0.f, sb = 0.f;
    #pragma unroll
    for (int i = 0; i < 8; i++) { sa += sh[i]; sb += sh[8 + i]; }
    oa = sa; ob = sb;
}

__device__ __forceinline__ uint32_t s2u(const void* p) {
    uint32_t a;
    asm("{ .reg .u64 t; cvta.to.shared.u64 t, %1; cvt.u32.u64 %0, t; }" : "=r"(a) : "l"(p));
    return a;
}
__device__ __forceinline__ void cpa16(uint32_t s, const void* g) {
    asm volatile("cp.async.cg.shared.global [%0], [%1], 16;" :: "r"(s), "l"(g));
}

// ---------------- shared bf16 HMMA mainloop, cp.async 2-stage ping-pong ----------------
// CTA 128x128, 8 warps = 2(M) x 4(N), warp tile 64x32 = 4x4 m16n8k16.
// A: [128 rows][K] stride strA; B: [128 rows(=N cols)][K] stride strB; nc chunks of K=32.
// sA/sB each hold 2 stages of 8192 bytes.
__device__ __forceinline__ void gemm_mainloop(
    const __nv_bfloat16* __restrict__ Ap, int strA,
    const __nv_bfloat16* __restrict__ Bp, int strB,
    int nc, __nv_bfloat16* sA, __nv_bfloat16* sB, float (&c)[4][4][4])
{
    int t = threadIdx.x, lane = t & 31, wid = t >> 5;
    int wm = wid & 1, wn = wid >> 1;
    uint32_t sAu = s2u(sA), sBu = s2u(sB);

    int lr = t >> 2, lg = t & 3;
    uint32_t sw0 = (uint32_t)(lr*64 + ((lg ^ ((lr>>1)&3)) << 4));
    int lr1 = lr + 64;
    uint32_t sw1 = (uint32_t)(lr1*64 + ((lg ^ ((lr1>>1)&3)) << 4));

    int qa = lane >> 3, ra = lane & 7;
    int a_m_local = (qa & 1)*8 + ra;
    int a_gsel = qa >> 1;
    int lb = lane & 15;
    int qb = lb >> 3, rb = lb & 7;

    const __nv_bfloat16* Ap0 = Ap + (size_t)lr *strA + lg*8;
    const __nv_bfloat16* Ap1 = Ap + (size_t)lr1*strA + lg*8;
    const __nv_bfloat16* Bp0 = Bp + (size_t)lr *strB + lg*8;
    const __nv_bfloat16* Bp1 = Bp + (size_t)lr1*strB + lg*8;

    // prologue: stage 0 <- chunk 0
    cpa16(sAu + sw0, Ap0);
    cpa16(sAu + sw1, Ap1);
    cpa16(sBu + sw0, Bp0);
    cpa16(sBu + sw1, Bp1);
    asm volatile("cp.async.commit_group;");

    for (int ck = 0; ck < nc; ck++) {
        asm volatile("cp.async.wait_group 0;");
        __syncthreads();
        if (ck + 1 < nc) {
            uint32_t st = ((ck + 1) & 1) * 8192;
            int o = (ck + 1)*32;
            cpa16(sAu + st + sw0, Ap0 + o);
            cpa16(sAu + st + sw1, Ap1 + o);
            cpa16(sBu + st + sw0, Bp0 + o);
            cpa16(sBu + st + sw1, Bp1 + o);
            asm volatile("cp.async.commit_group;");
        }
        uint32_t st8 = (ck & 1) * 8192;
        #pragma unroll
        for (int ks = 0; ks < 2; ks++) {
            uint32_t af[4][4];
            #pragma unroll
            for (int mt = 0; mt < 4; mt++) {
                int m = wm*64 + mt*16 + a_m_local;
                int g = ks*2 + a_gsel;
                uint32_t ad = sAu + st8 + (uint32_t)(m*64 + ((g ^ ((m>>1)&3)) << 4));
                asm volatile("ldmatrix.sync.aligned.m8n8.x4.shared.b16 {%0,%1,%2,%3}, [%4];"
                    : "=r"(af[mt][0]), "=r"(af[mt][1]), "=r"(af[mt][2]), "=r"(af[mt][3]) : "r"(ad));
            }
            uint32_t bf[4][2];
            #pragma unroll
            for (int nt = 0; nt < 4; nt++) {
                int n = wn*32 + nt*8 + rb;
                int g = ks*2 + qb;
                uint32_t bd = sBu + st8 + (uint32_t)(n*64 + ((g ^ ((n>>1)&3)) << 4));
                asm volatile("ldmatrix.sync.aligned.m8n8.x2.shared.b16 {%0,%1}, [%2];"
                    : "=r"(bf[nt][0]), "=r"(bf[nt][1]) : "r"(bd));
            }
            #pragma unroll
            for (int mt = 0; mt < 4; mt++)
                #pragma unroll
                for (int nt = 0; nt < 4; nt++) {
                    asm volatile(
                        "mma.sync.aligned.m16n8k16.row.col.f32.bf16.bf16.f32 "
                        "{%0,%1,%2,%3}, {%4,%5,%6,%7}, {%8,%9}, {%0,%1,%2,%3};"
                        : "+f"(c[mt][nt][0]), "+f"(c[mt][nt][1]), "+f"(c[mt][nt][2]), "+f"(c[mt][nt][3])
                        : "r"(af[mt][0]), "r"(af[mt][1]), "r"(af[mt][2]), "r"(af[mt][3]),
                          "r"(bf[nt][0]), "r"(bf[nt][1]));
                }
        }
    }
}

// ---------------- B split+transpose: g_bt[v][k'] from out_w ----------------
__global__ void __launch_bounds__(256) k_bsplit(const float* __restrict__ ow) {
    __shared__ float tile[32][33];
    int v0 = blockIdx.x * 32, k0 = blockIdx.y * 32;
    int tx = threadIdx.x & 31, ty = threadIdx.x >> 5;
    #pragma unroll
    for (int i = 0; i < 4; i++) {
        int k = k0 + ty + 8*i;
        tile[ty + 8*i][tx] = ow[(size_t)k*VV + v0 + tx] + ow[(size_t)(k + 256)*VV + v0 + tx];
    }
    __syncthreads();
    #pragma unroll
    for (int i = 0; i < 4; i++) {
        int v = v0 + ty + 8*i;
        float w = tile[tx][ty + 8*i];
        __nv_bfloat16 h = __float2bfloat16(w);
        __nv_bfloat16 l = __float2bfloat16(w - __bfloat162float(h));
        size_t base = (size_t)v*KP + k0 + tx;
        g_bt[base] = h;          // Wh
        g_bt[base + 256] = h;    // Wh (pairs with Al)
        g_bt[base + 512] = l;    // Wl (pairs with Ah)
    }
}

// ---------------- wmean for all layers ----------------
__global__ void k_wmean3(const float* __restrict__ W) {
    int l = blockIdx.x, t = threadIdx.x, lane = t & 31, w = t >> 5;
    for (int r = w; r < DD; r += 8) {
        const float* p = W + (size_t)l*DD*DD + (size_t)r*DD;
        float s = 0.f;
        #pragma unroll
        for (int j = 0; j < 8; j++) s += p[lane + 32*j];
        #pragma unroll
        for (int o = 16; o; o >>= 1) s += __shfl_xor_sync(0xffffffffu, s, o);
        if (lane == 0) g_wmean[l*DD + r] = s * (1.f/DD);
    }
}

// ---------------- embedding + phase space ----------------
__global__ void __launch_bounds__(256) k_phase(const int* __restrict__ x, const float* __restrict__ emb_real,
                        const float* __restrict__ lp, const float* __restrict__ iw,
                        const float* __restrict__ energy, const float* __restrict__ excf) {
    __shared__ float sh[16];
    int row = blockIdx.x, d = threadIdx.x;
    int tok = x[row];
    float re = emb_real[(size_t)tok*DD + d] * 0.1f;
    float fr = 0.f, fi = 0.f;
    const float cav[3] = {1.f, -0.5f, -0.5f};
    const float sav[3] = {0.f, 0.86602540378443865f, -0.86602540378443865f};
    const float PIPHI = 5.083203692315259f;
    #pragma unroll
    for (int i = 0; i < NLY; i++) {
        float pa = tanhf(lp[i*DD + d]) * PIPHI;
        float tr = re * cosf(pa);
        float ti = re * sinf(pa);
        float s1, s2;
        blockSum2(tr, tr*tr, sh, s1, s2);
        float mu = s1 * (1.f/DD);
        float r = (tr - mu) * rsqrtf(fmaxf(s2*(1.f/DD) - mu*mu, 0.f) + 1e-8f);
        blockSum2(ti, ti*ti, sh, s1, s2);
        mu = s1 * (1.f/DD);
        float im = (ti - mu) * rsqrtf(fmaxf(s2*(1.f/DD) - mu*mu, 0.f) + 1e-8f);
        float w = tanhf(iw[i*DD + d]);
        r *= w; im *= w;
        fr += r*cav[i] - im*sav[i];
        fi += r*sav[i] + im*cav[i];
    }
    float amp = sqrtf(fr*fr + fi*fi + 1e-8f);
    float exc = expf(energy[d]) * excf[0];
    if (amp < 0.1f) { fr += exc; fi += exc; }
    float nrm = rsqrtf(fr*fr + fi*fi + 1e-8f);
    g_real[row*DD + d] = clip1(fr * nrm);
    g_imag[row*DD + d] = clip1(fi * nrm);
}

// ---------------- per-layer: LN + operand staging (all coalesced) ----------------
__global__ void __launch_bounds__(256) k_norm(int layer, int first) {
    __shared__ float sh[16];
    int row = blockIdx.x, d = threadIdx.x;
    int idx = row*DD + d;
    float r = g_real[idx];
    float s1, s2;
    blockSum2(r, r*r, sh, s1, s2);
    float mu = s1 * (1.f/DD);
    float nr = (r - mu) * rsqrtf(fmaxf(s2*(1.f/DD) - mu*mu, 0.f) + 1e-5f);
    float ni;
    if (first) {
        float im = g_imag[idx];
        blockSum2(im, im*im, sh, s1, s2);
        mu = s1 * (1.f/DD);
        ni = (im - mu) * rsqrtf(fmaxf(s2*(1.f/DD) - mu*mu, 0.f) + 1e-5f);
    } else {
        ni = nr;   // imag == real after layer 0
    }
    float xx = nr + 1e-8f, yy = ni + 1e-8f;
    float h = rsqrtf(xx*xx + yy*yy);
    float cc = xx*h, ss = yy*h;   // cos/sin(atan2(yy,xx))
    g_c[idx] = cc; g_s[idx] = ss;
    float wm = g_wmean[layer*DD + d];
    g_cw[row*512 + d]       = __float2bfloat16(cc*wm);
    g_cw[row*512 + 256 + d] = __float2bfloat16(ss*wm);
    g_cs[row*512 + d]       = __float2bfloat16(cc);
    g_cs[row*512 + 256 + d] = __float2bfloat16(ss);
    g_nb[row*512 + d]       = __float2bfloat16(nr);
    g_nb[row*512 + 256 + d] = __float2bfloat16(ni);
}

// ---------------- per-layer: transpose g_nb -> g_nT (smem tiled) ----------------
__global__ void __launch_bounds__(256) k_trans() {
    __shared__ __nv_bfloat16 tl[32][33];
    int d0 = blockIdx.x*32, l0 = blockIdx.y*32, b = blockIdx.z;
    int tx = threadIdx.x & 31, ty = threadIdx.x >> 5;
    #pragma unroll
    for (int i = 0; i < 4; i++)
        tl[ty + 8*i][tx] = g_nb[(size_t)(b*LL + l0 + ty + 8*i)*512 + d0 + tx];
    __syncthreads();
    #pragma unroll
    for (int i = 0; i < 4; i++)
        g_nT[(size_t)b*512*LL + (size_t)(d0 + ty + 8*i)*LL + l0 + tx] = tl[tx][ty + 8*i];
}

// ---------------- per-layer: partial column sums for coherence ----------------
__global__ void k_colsum() {
    int b = blockIdx.x, ch = blockIdx.y, d = threadIdx.x;
    float sc = 0.f, ss = 0.f;
    #pragma unroll 4
    for (int m = ch*64; m < ch*64 + 64; m++) {
        int idx = (b*LL + m)*DD + d;
        sc += g_c[idx]; ss += g_s[idx];
    }
    g_scp[(b*6 + ch)*DD + d] = sc;
    g_ssp[(b*6 + ch)*DD + d] = ss;
}

// ---------------- per-layer: scores via HMMA (M=N=384, K=512 per batch) ----------------
__global__ void __launch_bounds__(256) k_scores_mma(const int* __restrict__ x) {
    __shared__ __align__(128) __nv_bfloat16 sA[2*128*32];
    __shared__ __align__(128) __nv_bfloat16 sB[2*128*32];
    int b = blockIdx.z, bm = blockIdx.y*128, bn = blockIdx.x*128;
    float c[4][4][4];
    #pragma unroll
    for (int i = 0; i < 4; i++)
        #pragma unroll
        for (int j = 0; j < 4; j++)
            #pragma unroll
            for (int q = 0; q < 4; q++) c[i][j][q] = 0.f;
    gemm_mainloop(g_cw + (size_t)(b*LL + bm)*512, 512,
                  g_cs + (size_t)(b*LL + bn)*512, 512,
                  16, sA, sB, c);
    int lane = threadIdx.x & 31, wid = threadIdx.x >> 5;
    int wm = wid & 1, wn = wid >> 1;
    int rr0 = lane >> 2, cc0 = (lane & 3)*2;
    #pragma unroll
    for (int mt = 0; mt < 4; mt++)
        #pragma unroll
        for (int nt = 0; nt < 4; nt++) {
            int row = bm + wm*64 + mt*16 + rr0;
            int col = bn + wn*32 + nt*8 + cc0;
            bool p0 = (x[b*LL + col] == 0), p1 = (x[b*LL + col + 1] == 0);
            float2 o;
            o.x = p0 ? (-CUDART_INF_F) : c[mt][nt][0]*0.0625f;
            o.y = p1 ? (-CUDART_INF_F) : c[mt][nt][1]*0.0625f;
            *(float2*)&g_scores[(size_t)(b*LL + row)*LL + col] = o;
            o.x = p0 ? (-CUDART_INF_F) : c[mt][nt][2]*0.0625f;
            o.y = p1 ? (-CUDART_INF_F) : c[mt][nt][3]*0.0625f;
            *(float2*)&g_scores[(size_t)(b*LL + row + 8)*LL + col] = o;
        }
}

// ---------------- per-layer: softmax + clip -> bf16 attn ----------------
__global__ void k_softmax() {
    __shared__ float sh[128];
    int row = blockIdx.x, t = threadIdx.x;
    const float* sc = &g_scores[(size_t)row*LL];
    float v[3], mx = -CUDART_INF_F;
    #pragma unroll
    for (int r = 0; r < 3; r++) { v[r] = sc[t + 128*r]; mx = fmaxf(mx, v[r]); }
    sh[t] = mx; __syncthreads();
    #pragma unroll
    for (int s = 64; s > 0; s >>= 1) { if (t < s) sh[t] = fmaxf(sh[t], sh[t+s]); __syncthreads(); }
    mx = sh[0]; __syncthreads();
    float sum = 0.f;
    #pragma unroll
    for (int r = 0; r < 3; r++) { v[r] = expf(v[r] - mx); sum += v[r]; }
    sh[t] = sum; __syncthreads();
    #pragma unroll
    for (int s = 64; s > 0; s >>= 1) { if (t < s) sh[t] += sh[t+s]; __syncthreads(); }
    float inv = 1.f / sh[0];
    #pragma unroll
    for (int r = 0; r < 3; r++) {
        float p = fminf(fmaxf(v[r]*inv, 1e-6f), 1.f);
        g_attnb[(size_t)row*LL + t + 128*r] = __float2bfloat16(p);
    }
}

// ---------------- per-layer: out = attn @ [nr|ni]^T via HMMA ----------------
__global__ void __launch_bounds__(256) k_out_mma() {
    __shared__ __align__(128) __nv_bfloat16 sA[2*128*32];
    __shared__ __align__(128) __nv_bfloat16 sB[2*128*32];
    int b = blockIdx.z, bm = blockIdx.y*128, bn = blockIdx.x*128;
    float c[4][4][4];
    #pragma unroll
    for (int i = 0; i < 4; i++)
        #pragma unroll
        for (int j = 0; j < 4; j++)
            #pragma unroll
            for (int q = 0; q < 4; q++) c[i][j][q] = 0.f;
    gemm_mainloop(g_attnb + (size_t)(b*LL + bm)*LL, LL,
                  g_nT + (size_t)b*512*LL + (size_t)bn*LL, LL,
                  12, sA, sB, c);
    int lane = threadIdx.x & 31, wid = threadIdx.x >> 5;
    int wm = wid & 1, wn = wid >> 1;
    int rr0 = lane >> 2, cc0 = (lane & 3)*2;
    float* dst = (bn < 256) ? g_outr : g_outi;
    int nb = (bn < 256) ? bn : (bn - 256);
    #pragma unroll
    for (int mt = 0; mt < 4; mt++)
        #pragma unroll
        for (int nt = 0; nt < 4; nt++) {
            int row = bm + wm*64 + mt*16 + rr0;
            int col = nb + wn*32 + nt*8 + cc0;
            float2 o;
            o.x = c[mt][nt][0]; o.y = c[mt][nt][1];
            *(float2*)&dst[(size_t)(b*LL + row)*DD + col] = o;
            o.x = c[mt][nt][2]; o.y = c[mt][nt][3];
            *(float2*)&dst[(size_t)(b*LL + row + 8)*DD + col] = o;
        }
}

// ---------------- per-layer: coherence + phase preservation + residual LN ----------------
// last!=0: also perform the final LN + bf16 hi/lo split (fused k_prepA)
__global__ void __launch_bounds__(256) k_update(const float* __restrict__ pp, const float* __restrict__ cohf,
                                                int layer, int last) {
    __shared__ float sh[16];
    int row = blockIdx.x, d = threadIdx.x;
    int b = row / LL;
    float SC = 0.f, SS = 0.f;
    #pragma unroll
    for (int ch = 0; ch < 6; ch++) {
        SC += g_scp[(b*6 + ch)*DD + d];
        SS += g_ssp[(b*6 + ch)*DD + d];
    }
    float part = g_c[row*DD + d]*SC + g_s[row*DD + d]*SS;
    float s1, s2;
    blockSum2(part, part, sh, s1, s2);
    float coh = s1 * (1.f / (float)(LL*DD));
    float cfv = sigm(cohf[layer]) * coh;
    float orv = g_outr[row*DD + d], oiv = g_outi[row*DD + d];
    float phase = atan2f(oiv + 1e-8f, orv + 1e-8f);
    float pres = sigm(pp[layer*DD + d]) * cfv;
    float pr = orv * cosf(phase * pres);
    float val = g_real[row*DD + d] + 0.01f * pr;
    blockSum2(val, val*val, sh, s1, s2);
    float mu = s1 * (1.f/DD);
    float r = clip1((val - mu) * rsqrtf(fmaxf(s2*(1.f/DD) - mu*mu, 0.f) + 1e-8f));
    if (!last) {
        g_real[row*DD + d] = r;      // g_imag is never read after layer 0 -> dead store removed
    } else {
        // fused final LN + bf16 hi/lo split
        blockSum2(r, r*r, sh, s1, s2);
        mu = s1 * (1.f/DD);
        float a = (r - mu) * rsqrtf(fmaxf(s2*(1.f/DD) - mu*mu, 0.f) + 1e-5f);
        __nv_bfloat16 h = __float2bfloat16(a);
        __nv_bfloat16 l = __float2bfloat16(a - __bfloat162float(h));
        size_t base = (size_t)row*KP + d;
        g_aexp[base] = h;
        g_aexp[base + 256] = l;
        g_aexp[base + 512] = h;
    }
}

// ---------------- final GEMM via HMMA: C[768,32000] ----------------
__global__ void __launch_bounds__(256) k_gemm_mma(const float* __restrict__ bias, float* __restrict__ out) {
    __shared__ __align__(128) __nv_bfloat16 sA[2*128*32];
    __shared__ __align__(128) __nv_bfloat16 sB[2*128*32];
    int bn = blockIdx.x * 128, bm = blockIdx.y * 128;
    float c[4][4][4];
    #pragma unroll
    for (int i = 0; i < 4; i++)
        #pragma unroll
        for (int j = 0; j < 4; j++)
            #pragma unroll
            for (int q = 0; q < 4; q++) c[i][j][q] = 0.f;
    gemm_mainloop(g_aexp + (size_t)bm*KP, KP,
                  g_bt + (size_t)bn*KP, KP,
                  24, sA, sB, c);
    int lane = threadIdx.x & 31, wid = threadIdx.x >> 5;
    int wm = wid & 1, wn = wid >> 1;
    int rr0 = lane >> 2, cc0 = (lane & 3)*2;
    #pragma unroll
    for (int mt = 0; mt < 4; mt++) {
        #pragma unroll
        for (int nt = 0; nt < 4; nt++) {
            int row = bm + wm*64 + mt*16 + rr0;
            int col = bn + wn*32 + nt*8 + cc0;
            float b0 = bias[col], b1 = bias[col + 1];
            float2 o;
            o.x = fminf(fmaxf((c[mt][nt][0] + b0)*0.1f, -10.f), 10.f);
            o.y = fminf(fmaxf((c[mt][nt][1] + b1)*0.1f, -10.f), 10.f);
            *(float2*)&out[(size_t)row*VV + col] = o;
            o.x = fminf(fmaxf((c[mt][nt][2] + b0)*0.1f, -10.f), 10.f);
            o.y = fminf(fmaxf((c[mt][nt][3] + b1)*0.1f, -10.f), 10.f);
            *(float2*)&out[(size_t)(row + 8)*VV + col] = o;
        }
    }
}

// ---------------- launch ----------------
extern "C" void kernel_launch(void* const* d_in, const int* in_sizes, int n_in,
                              void* d_out, int out_size) {
    const int*   x        = (const int*)  d_in[0];
    const float* emb_real = (const float*)d_in[1];
    // d_in[2] = emb_imag: unused downstream (as in reference)
    const float* lp       = (const float*)d_in[3];
    const float* iw       = (const float*)d_in[4];
    const float* energy   = (const float*)d_in[5];
    const float* excf     = (const float*)d_in[6];
    const float* pp       = (const float*)d_in[7];
    const float* cohf     = (const float*)d_in[8];
    const float* Wattn    = (const float*)d_in[9];
    const float* out_w    = (const float*)d_in[10];
    const float* out_b    = (const float*)d_in[11];
    float* out = (float*)d_out;

    k_bsplit<<<dim3(VV/32, DD/32), 256>>>(out_w);
    k_wmean3<<<NLY, 256>>>(Wattn);
    k_phase<<<BL, 256>>>(x, emb_real, lp, iw, energy, excf);
    for (int i = 0; i < NLY; i++) {
        k_norm<<<BL, 256>>>(i, i == 0 ? 1 : 0);
        k_trans<<<dim3(512/32, LL/32, BB), 256>>>();
        k_colsum<<<dim3(BB, 6), 256>>>();
        k_scores_mma<<<dim3(LL/128, LL/128, BB), 256>>>(x);
        k_softmax<<<BL, 128>>>();
        k_out_mma<<<dim3(512/128, LL/128, BB), 256>>>();
        k_update<<<BL, 256>>>(pp, cohf, i, i == NLY - 1 ? 1 : 0);
    }
    k_gemm_mma<<<dim3(VV/128, BL/128), 256>>>(out_b, out);
}